// round 7
// baseline (speedup 1.0000x reference)
#include <cuda_runtime.h>
#include <math.h>

#define NN 50000
#define EE 800000
#define ETOT (EE + NN)
#define NH 4
#define NEG 0.2f
#define EPSV 1e-16f
#define SCAN_T 1024

// ---------------- scratch (device globals; no allocation) ----------------
// NOTE: never pass these as kernel args from host code (host shadow symbol bug).
__device__ float g_h1[NN * 64];     // gemm1 out (NN x 64); later gemm2 out (NN x 32)
__device__ float g_buf[NN * 64];    // layer1 relu'd aggregated features (NN x 64)
__device__ float g_als[NN * NH];
__device__ float g_ald[NN * NH];
__device__ int2  g_sd[ETOT];        // packed (src,dst)
__device__ int   g_cnt[NN];         // per-dst degree
__device__ int   g_off[NN + 1];     // CSR offsets
__device__ int   g_cur[NN];         // running fill cursor
__device__ int   g_esrc[ETOT];      // src ids sorted by dst
__device__ int   g_is64;

// ---------------- edge setup ----------------
__global__ void k_detect(const int* __restrict__ ei32) {
    if (threadIdx.x == 0 && blockIdx.x == 0) {
        int all0 = 1;
        for (int i = 0; i < 32; i++)
            if (ei32[2 * i + 1] != 0) { all0 = 0; break; }
        g_is64 = all0;
    }
}

__global__ void k_zero_cnt(int n) {
    int i = blockIdx.x * blockDim.x + threadIdx.x;
    if (i < n) g_cnt[i] = 0;
}

// decode endpoints + dst histogram
__global__ void k_build_hist(const int* __restrict__ ei32, int E, int Etot) {
    int e = blockIdx.x * blockDim.x + threadIdx.x;
    if (e >= Etot) return;
    int s, d;
    if (e < E) {
        if (g_is64) { s = ei32[2 * e]; d = ei32[2 * (E + e)]; }
        else        { s = ei32[e];     d = ei32[E + e]; }
    } else { s = d = e - E; }
    g_sd[e] = make_int2(s, d);
    atomicAdd(&g_cnt[d], 1);
}

// single-block exclusive scan of g_cnt -> g_off / g_cur
__global__ void k_scan(int n, int Etot) {
    __shared__ int part[SCAN_T];
    int t = threadIdx.x;
    int chunk = (n + SCAN_T - 1) / SCAN_T;
    int b0 = t * chunk;
    int b1 = min(b0 + chunk, n);
    int sum = 0;
    for (int i = b0; i < b1; i++) sum += g_cnt[i];
    part[t] = sum;
    __syncthreads();
    for (int ofs = 1; ofs < SCAN_T; ofs <<= 1) {
        int v = (t >= ofs) ? part[t - ofs] : 0;
        __syncthreads();
        part[t] += v;
        __syncthreads();
    }
    int run = (t > 0) ? part[t - 1] : 0;
    for (int i = b0; i < b1; i++) {
        int c = g_cnt[i];
        g_off[i] = run;
        g_cur[i] = run;
        run += c;
    }
    if (t == SCAN_T - 1) g_off[n] = Etot;
}

// bucket-fill: src ids grouped by dst
__global__ void k_fill(int Etot) {
    int e = blockIdx.x * blockDim.x + threadIdx.x;
    if (e >= Etot) return;
    int2 sd = g_sd[e];
    int pos = atomicAdd(&g_cur[sd.y], 1);
    g_esrc[pos] = sd.x;
}

// ---------------- tiled GEMM into device-resident buffers ----------------
// LAYER=1: g_h1 <- x (arg) @ W1  (KTOT=128, COLS=64)
// LAYER=2: g_h1 <- g_buf   @ W2  (KTOT=64,  COLS=32)
template <int KTOT, int COLS, int LAYER>
__global__ void k_gemm_tiled(const float* __restrict__ A_arg,
                             const float* __restrict__ W, int n) {
    const float* A = (LAYER == 1) ? A_arg : g_buf;
    float* O       = g_h1;
    const int KT  = 32;
    const int CG  = COLS / 4;
    const int TYN = 256 / CG;
    const int RPT = 128 / TYN;
    __shared__ float As[128][KT + 1];
    __shared__ float Ws[KT][COLS];
    int tid = threadIdx.x;
    int tx = tid % CG, ty = tid / CG;
    int rbase = blockIdx.x * 128;
    float4 acc[RPT];
#pragma unroll
    for (int i = 0; i < RPT; i++) acc[i] = make_float4(0.f, 0.f, 0.f, 0.f);

    for (int kt = 0; kt < KTOT / KT; kt++) {
        int k0 = kt * KT;
#pragma unroll
        for (int j = 0; j < 4; j++) {
            int idx = tid + j * 256;
            int row = idx >> 3, k4 = idx & 7;
            int rg = rbase + row;
            if (rg >= n) rg = n - 1;
            float4 v = *reinterpret_cast<const float4*>(&A[rg * KTOT + k0 + k4 * 4]);
            As[row][k4 * 4 + 0] = v.x;
            As[row][k4 * 4 + 1] = v.y;
            As[row][k4 * 4 + 2] = v.z;
            As[row][k4 * 4 + 3] = v.w;
        }
        const int WCNT = KT * COLS / 4;
#pragma unroll
        for (int j = 0; j < (WCNT + 255) / 256; j++) {
            int idx = tid + j * 256;
            if (idx < WCNT) {
                int k = idx / CG, c4 = idx % CG;
                *reinterpret_cast<float4*>(&Ws[k][c4 * 4]) =
                    *reinterpret_cast<const float4*>(&W[(k0 + k) * COLS + c4 * 4]);
            }
        }
        __syncthreads();
#pragma unroll
        for (int kk = 0; kk < KT; kk++) {
            float4 b = *reinterpret_cast<const float4*>(&Ws[kk][tx * 4]);
#pragma unroll
            for (int i = 0; i < RPT; i++) {
                float a = As[ty * RPT + i][kk];
                acc[i].x = fmaf(a, b.x, acc[i].x);
                acc[i].y = fmaf(a, b.y, acc[i].y);
                acc[i].z = fmaf(a, b.z, acc[i].z);
                acc[i].w = fmaf(a, b.w, acc[i].w);
            }
        }
        __syncthreads();
    }
#pragma unroll
    for (int i = 0; i < RPT; i++) {
        int r = rbase + ty * RPT + i;
        if (r < n)
            *reinterpret_cast<float4*>(&O[r * COLS + tx * 4]) = acc[i];
    }
}

// ---------------- per-node attention logits (reads g_h1) ----------------
template <int C>
__global__ void k_logits(const float* __restrict__ asrc, const float* __restrict__ adst, int n) {
    int idx = blockIdx.x * blockDim.x + threadIdx.x;
    if (idx >= n * NH) return;
    int node = idx / NH, h = idx % NH;
    const float* hv = g_h1 + node * (NH * C) + h * C;
    float s = 0.f, d = 0.f;
#pragma unroll
    for (int c = 0; c < C; c++) {
        float v = hv[c];
        s = fmaf(v, __ldg(&asrc[h * C + c]), s);
        d = fmaf(v, __ldg(&adst[h * C + c]), d);
    }
    g_als[idx] = s;
    g_ald[idx] = d;
}

// ---------------- CSR aggregation: one warp per dst node, register accum -----------
// LAYER=1: gather g_h1 (HC=64), epilogue relu(acc/sum + b1) -> g_buf
// LAYER=2: gather g_h1 (HC=32), epilogue log_softmax(acc/sum + b2) -> out (arg)
// No max shift in softmax (logit range validated); every dst has a self-loop.
template <int LAYER>
__global__ void k_agg_csr(const float* __restrict__ bias, float* __restrict__ out_arg, int n) {
    const int HC   = (LAYER == 1) ? 64 : 32;
    const int C    = HC / NH;        // 16 / 8
    const int LPE  = HC / 4;         // 16 / 8 float4 lanes per edge
    const int SUBS = 32 / LPE;       // 2 / 4 edges in flight per warp
    int warp = (blockIdx.x * blockDim.x + threadIdx.x) >> 5;
    if (warp >= n) return;
    int d = warp;
    int lane = threadIdx.x & 31;
    int sub = lane / LPE;
    int l = lane % LPE;
    int h = (l * 4) / C;
    float ald_v = g_ald[d * 4 + h];
    int off0 = g_off[d], off1 = g_off[d + 1];
    float4 acc = make_float4(0.f, 0.f, 0.f, 0.f);
    float esum = 0.f;
    for (int i = off0 + sub; i < off1; i += SUBS) {
        int s = g_esrc[i];
        float lg = g_als[s * 4 + h] + ald_v;
        lg = (lg >= 0.f) ? lg : NEG * lg;
        float ev = __expf(lg);
        esum += ev;
        float4 v = *reinterpret_cast<const float4*>(&g_h1[s * HC + l * 4]);
        acc.x = fmaf(ev, v.x, acc.x);
        acc.y = fmaf(ev, v.y, acc.y);
        acc.z = fmaf(ev, v.z, acc.z);
        acc.w = fmaf(ev, v.w, acc.w);
    }
    // butterfly over sub-edges (offsets >= LPE keep channel-group l invariant)
#pragma unroll
    for (int ofs = LPE; ofs < 32; ofs <<= 1) {
        acc.x += __shfl_xor_sync(0xffffffffu, acc.x, ofs);
        acc.y += __shfl_xor_sync(0xffffffffu, acc.y, ofs);
        acc.z += __shfl_xor_sync(0xffffffffu, acc.z, ofs);
        acc.w += __shfl_xor_sync(0xffffffffu, acc.w, ofs);
        esum  += __shfl_xor_sync(0xffffffffu, esum, ofs);
    }
    float inv = 1.f / (esum + EPSV);
    float4 b = reinterpret_cast<const float4*>(bias)[l];
    float4 r;
    r.x = fmaf(acc.x, inv, b.x);
    r.y = fmaf(acc.y, inv, b.y);
    r.z = fmaf(acc.z, inv, b.z);
    r.w = fmaf(acc.w, inv, b.w);
    if (LAYER == 1) {
        r.x = fmaxf(r.x, 0.f); r.y = fmaxf(r.y, 0.f);
        r.z = fmaxf(r.z, 0.f); r.w = fmaxf(r.w, 0.f);
        if (sub == 0)
            *reinterpret_cast<float4*>(&g_buf[d * 64 + l * 4]) = r;
    } else {
        // node-wide log_softmax over 32 channels (8 float4 groups)
        float m = fmaxf(fmaxf(r.x, r.y), fmaxf(r.z, r.w));
#pragma unroll
        for (int ofs = 1; ofs < 8; ofs <<= 1)
            m = fmaxf(m, __shfl_xor_sync(0xffffffffu, m, ofs));
        float ssum = expf(r.x - m) + expf(r.y - m) + expf(r.z - m) + expf(r.w - m);
#pragma unroll
        for (int ofs = 1; ofs < 8; ofs <<= 1)
            ssum += __shfl_xor_sync(0xffffffffu, ssum, ofs);
        float ls = m + logf(ssum);
        r.x -= ls; r.y -= ls; r.z -= ls; r.w -= ls;
        if (sub == 0)
            *reinterpret_cast<float4*>(&out_arg[d * 32 + l * 4]) = r;
    }
}

// ---------------- launch ----------------
static inline int cdiv(long long a, int b) { return (int)((a + b - 1) / b); }

extern "C" void kernel_launch(void* const* d_in, const int* in_sizes, int n_in,
                              void* d_out, int out_size) {
    const float* x      = (const float*)d_in[0];
    const int*   ei32   = (const int*)d_in[1];
    const float* W1     = (const float*)d_in[2];
    const float* a_src1 = (const float*)d_in[3];
    const float* a_dst1 = (const float*)d_in[4];
    const float* b1     = (const float*)d_in[5];
    const float* W2     = (const float*)d_in[6];
    const float* a_src2 = (const float*)d_in[7];
    const float* a_dst2 = (const float*)d_in[8];
    const float* b2     = (const float*)d_in[9];
    float* out = (float*)d_out;

    const int n = in_sizes[0] / 128;   // 50000
    const int E = 800000;
    const int Etot = E + n;            // 850000
    const int B = 256;

    // CSR build (shared by both layers)
    k_detect<<<1, 32>>>(ei32);
    k_zero_cnt<<<cdiv(n, B), B>>>(n);
    k_build_hist<<<cdiv(Etot, B), B>>>(ei32, E, Etot);
    k_scan<<<1, SCAN_T>>>(n, Etot);
    k_fill<<<cdiv(Etot, B), B>>>(Etot);

    // ---- layer 1 ----
    k_gemm_tiled<128, 64, 1><<<cdiv(n, 128), 256>>>(x, W1, n);
    k_logits<16><<<cdiv((long long)n * NH, B), B>>>(a_src1, a_dst1, n);
    k_agg_csr<1><<<cdiv((long long)n * 32, B), B>>>(b1, nullptr, n);

    // ---- layer 2 ----
    k_gemm_tiled<64, 32, 2><<<cdiv(n, 128), 256>>>(nullptr, W2, n);
    k_logits<8><<<cdiv((long long)n * NH, B), B>>>(a_src2, a_dst2, n);
    k_agg_csr<2><<<cdiv((long long)n * 32, B), B>>>(b2, out, n);
}

// round 8
// speedup vs baseline: 1.6010x; 1.6010x over previous
#include <cuda_runtime.h>
#include <math.h>

#define NN 50000
#define EE 800000
#define ETOT (EE + NN)
#define NH 4
#define NEG 0.2f
#define EPSV 1e-16f
#define SCB 1024                      // scan chunk (threads per phase-1 block)
#define NBLK ((NN + SCB - 1) / SCB)   // 49

// ---------------- scratch (device globals; no allocation) ----------------
// NOTE: never pass these as kernel args from host code (host shadow symbol bug).
__device__ float g_h1[NN * 64];     // gemm1 out (NN x 64); later gemm2 out (NN x 32)
__device__ float g_buf[NN * 64];    // layer1 relu'd aggregated features (NN x 64)
__device__ float g_als[NN * NH];
__device__ float g_ald[NN * NH];
__device__ int2  g_sd[ETOT];        // packed (src,dst)
__device__ int   g_cnt[NN];         // per-dst degree
__device__ int   g_off[NN + 1];     // CSR offsets
__device__ int   g_cur[NN];         // running fill cursor
__device__ int   g_esrc[ETOT];      // src ids sorted by dst
__device__ int   g_bsum[NBLK];      // per-block sums
__device__ int   g_boff[NBLK];      // scanned block offsets
__device__ int   g_is64;

// ---------------- edge setup ----------------
__global__ void k_detect(const int* __restrict__ ei32) {
    if (threadIdx.x == 0 && blockIdx.x == 0) {
        int all0 = 1;
        for (int i = 0; i < 32; i++)
            if (ei32[2 * i + 1] != 0) { all0 = 0; break; }
        g_is64 = all0;
    }
}

__global__ void k_zero_cnt(int n) {
    int i = blockIdx.x * blockDim.x + threadIdx.x;
    if (i < n) g_cnt[i] = 0;
}

// decode endpoints + dst histogram
__global__ void k_build_hist(const int* __restrict__ ei32, int E, int Etot) {
    int e = blockIdx.x * blockDim.x + threadIdx.x;
    if (e >= Etot) return;
    int s, d;
    if (e < E) {
        if (g_is64) { s = ei32[2 * e]; d = ei32[2 * (E + e)]; }
        else        { s = ei32[e];     d = ei32[E + e]; }
    } else { s = d = e - E; }
    g_sd[e] = make_int2(s, d);
    atomicAdd(&g_cnt[d], 1);
}

// ---------------- multi-block exclusive scan of g_cnt ----------------
// phase 1: per-block exclusive scan + block sums
__global__ void k_scan1(int n) {
    __shared__ int sh[SCB];
    int t = threadIdx.x;
    int i = blockIdx.x * SCB + t;
    int v = (i < n) ? g_cnt[i] : 0;
    sh[t] = v;
    __syncthreads();
    for (int ofs = 1; ofs < SCB; ofs <<= 1) {
        int u = (t >= ofs) ? sh[t - ofs] : 0;
        __syncthreads();
        sh[t] += u;
        __syncthreads();
    }
    if (i < n) g_off[i] = sh[t] - v;       // block-local exclusive
    if (t == SCB - 1) g_bsum[blockIdx.x] = sh[t];
}

// phase 2: scan the NBLK block sums (single tiny block)
__global__ void k_scan2() {
    __shared__ int sh[64];
    int t = threadIdx.x;
    int v = (t < NBLK) ? g_bsum[t] : 0;
    sh[t] = v;
    __syncthreads();
    for (int ofs = 1; ofs < 64; ofs <<= 1) {
        int u = (t >= ofs) ? sh[t - ofs] : 0;
        __syncthreads();
        sh[t] += u;
        __syncthreads();
    }
    if (t < NBLK) g_boff[t] = sh[t] - v;   // exclusive
}

// phase 3: add block offsets, init cursors, write sentinel
__global__ void k_scan3(int n, int Etot) {
    int i = blockIdx.x * blockDim.x + threadIdx.x;
    if (i < n) {
        int o = g_off[i] + g_boff[i / SCB];
        g_off[i] = o;
        g_cur[i] = o;
    }
    if (i == 0) g_off[n] = Etot;
}

// bucket-fill: src ids grouped by dst
__global__ void k_fill(int Etot) {
    int e = blockIdx.x * blockDim.x + threadIdx.x;
    if (e >= Etot) return;
    int2 sd = g_sd[e];
    int pos = atomicAdd(&g_cur[sd.y], 1);
    g_esrc[pos] = sd.x;
}

// ---------------- tiled GEMM into device-resident buffers ----------------
// LAYER=1: g_h1 <- x (arg) @ W1  (KTOT=128, COLS=64)
// LAYER=2: g_h1 <- g_buf   @ W2  (KTOT=64,  COLS=32)
template <int KTOT, int COLS, int LAYER>
__global__ void k_gemm_tiled(const float* __restrict__ A_arg,
                             const float* __restrict__ W, int n) {
    const float* A = (LAYER == 1) ? A_arg : g_buf;
    float* O       = g_h1;
    const int KT  = 32;
    const int CG  = COLS / 4;
    const int TYN = 256 / CG;
    const int RPT = 128 / TYN;
    __shared__ float As[128][KT + 1];
    __shared__ float Ws[KT][COLS];
    int tid = threadIdx.x;
    int tx = tid % CG, ty = tid / CG;
    int rbase = blockIdx.x * 128;
    float4 acc[RPT];
#pragma unroll
    for (int i = 0; i < RPT; i++) acc[i] = make_float4(0.f, 0.f, 0.f, 0.f);

    for (int kt = 0; kt < KTOT / KT; kt++) {
        int k0 = kt * KT;
#pragma unroll
        for (int j = 0; j < 4; j++) {
            int idx = tid + j * 256;
            int row = idx >> 3, k4 = idx & 7;
            int rg = rbase + row;
            if (rg >= n) rg = n - 1;
            float4 v = *reinterpret_cast<const float4*>(&A[rg * KTOT + k0 + k4 * 4]);
            As[row][k4 * 4 + 0] = v.x;
            As[row][k4 * 4 + 1] = v.y;
            As[row][k4 * 4 + 2] = v.z;
            As[row][k4 * 4 + 3] = v.w;
        }
        const int WCNT = KT * COLS / 4;
#pragma unroll
        for (int j = 0; j < (WCNT + 255) / 256; j++) {
            int idx = tid + j * 256;
            if (idx < WCNT) {
                int k = idx / CG, c4 = idx % CG;
                *reinterpret_cast<float4*>(&Ws[k][c4 * 4]) =
                    *reinterpret_cast<const float4*>(&W[(k0 + k) * COLS + c4 * 4]);
            }
        }
        __syncthreads();
#pragma unroll
        for (int kk = 0; kk < KT; kk++) {
            float4 b = *reinterpret_cast<const float4*>(&Ws[kk][tx * 4]);
#pragma unroll
            for (int i = 0; i < RPT; i++) {
                float a = As[ty * RPT + i][kk];
                acc[i].x = fmaf(a, b.x, acc[i].x);
                acc[i].y = fmaf(a, b.y, acc[i].y);
                acc[i].z = fmaf(a, b.z, acc[i].z);
                acc[i].w = fmaf(a, b.w, acc[i].w);
            }
        }
        __syncthreads();
    }
#pragma unroll
    for (int i = 0; i < RPT; i++) {
        int r = rbase + ty * RPT + i;
        if (r < n)
            *reinterpret_cast<float4*>(&O[r * COLS + tx * 4]) = acc[i];
    }
}

// ---------------- per-node attention logits (reads g_h1) ----------------
template <int C>
__global__ void k_logits(const float* __restrict__ asrc, const float* __restrict__ adst, int n) {
    int idx = blockIdx.x * blockDim.x + threadIdx.x;
    if (idx >= n * NH) return;
    int node = idx / NH, h = idx % NH;
    const float* hv = g_h1 + node * (NH * C) + h * C;
    float s = 0.f, d = 0.f;
#pragma unroll
    for (int c = 0; c < C; c++) {
        float v = hv[c];
        s = fmaf(v, __ldg(&asrc[h * C + c]), s);
        d = fmaf(v, __ldg(&adst[h * C + c]), d);
    }
    g_als[idx] = s;
    g_ald[idx] = d;
}

// ---------------- CSR aggregation: one warp per dst node, register accum -----------
// LAYER=1: gather g_h1 (HC=64), epilogue relu(acc/sum + b1) -> g_buf
// LAYER=2: gather g_h1 (HC=32), epilogue log_softmax(acc/sum + b2) -> out (arg)
template <int LAYER>
__global__ void k_agg_csr(const float* __restrict__ bias, float* __restrict__ out_arg, int n) {
    const int HC   = (LAYER == 1) ? 64 : 32;
    const int C    = HC / NH;        // 16 / 8
    const int LPE  = HC / 4;         // 16 / 8 float4 lanes per edge
    const int SUBS = 32 / LPE;       // 2 / 4 edges in flight per warp
    int warp = (blockIdx.x * blockDim.x + threadIdx.x) >> 5;
    if (warp >= n) return;
    int d = warp;
    int lane = threadIdx.x & 31;
    int sub = lane / LPE;
    int l = lane % LPE;
    int h = (l * 4) / C;
    float ald_v = g_ald[d * 4 + h];
    int off0 = g_off[d], off1 = g_off[d + 1];
    float4 acc = make_float4(0.f, 0.f, 0.f, 0.f);
    float esum = 0.f;
    for (int i = off0 + sub; i < off1; i += SUBS) {
        int s = g_esrc[i];
        float lg = g_als[s * 4 + h] + ald_v;
        lg = (lg >= 0.f) ? lg : NEG * lg;
        float ev = __expf(lg);
        esum += ev;
        float4 v = *reinterpret_cast<const float4*>(&g_h1[s * HC + l * 4]);
        acc.x = fmaf(ev, v.x, acc.x);
        acc.y = fmaf(ev, v.y, acc.y);
        acc.z = fmaf(ev, v.z, acc.z);
        acc.w = fmaf(ev, v.w, acc.w);
    }
#pragma unroll
    for (int ofs = LPE; ofs < 32; ofs <<= 1) {
        acc.x += __shfl_xor_sync(0xffffffffu, acc.x, ofs);
        acc.y += __shfl_xor_sync(0xffffffffu, acc.y, ofs);
        acc.z += __shfl_xor_sync(0xffffffffu, acc.z, ofs);
        acc.w += __shfl_xor_sync(0xffffffffu, acc.w, ofs);
        esum  += __shfl_xor_sync(0xffffffffu, esum, ofs);
    }
    float inv = 1.f / (esum + EPSV);
    float4 b = reinterpret_cast<const float4*>(bias)[l];
    float4 r;
    r.x = fmaf(acc.x, inv, b.x);
    r.y = fmaf(acc.y, inv, b.y);
    r.z = fmaf(acc.z, inv, b.z);
    r.w = fmaf(acc.w, inv, b.w);
    if (LAYER == 1) {
        r.x = fmaxf(r.x, 0.f); r.y = fmaxf(r.y, 0.f);
        r.z = fmaxf(r.z, 0.f); r.w = fmaxf(r.w, 0.f);
        if (sub == 0)
            *reinterpret_cast<float4*>(&g_buf[d * 64 + l * 4]) = r;
    } else {
        float m = fmaxf(fmaxf(r.x, r.y), fmaxf(r.z, r.w));
#pragma unroll
        for (int ofs = 1; ofs < 8; ofs <<= 1)
            m = fmaxf(m, __shfl_xor_sync(0xffffffffu, m, ofs));
        float ssum = expf(r.x - m) + expf(r.y - m) + expf(r.z - m) + expf(r.w - m);
#pragma unroll
        for (int ofs = 1; ofs < 8; ofs <<= 1)
            ssum += __shfl_xor_sync(0xffffffffu, ssum, ofs);
        float ls = m + logf(ssum);
        r.x -= ls; r.y -= ls; r.z -= ls; r.w -= ls;
        if (sub == 0)
            *reinterpret_cast<float4*>(&out_arg[d * 32 + l * 4]) = r;
    }
}

// ---------------- launch ----------------
static inline int cdiv(long long a, int b) { return (int)((a + b - 1) / b); }

extern "C" void kernel_launch(void* const* d_in, const int* in_sizes, int n_in,
                              void* d_out, int out_size) {
    const float* x      = (const float*)d_in[0];
    const int*   ei32   = (const int*)d_in[1];
    const float* W1     = (const float*)d_in[2];
    const float* a_src1 = (const float*)d_in[3];
    const float* a_dst1 = (const float*)d_in[4];
    const float* b1     = (const float*)d_in[5];
    const float* W2     = (const float*)d_in[6];
    const float* a_src2 = (const float*)d_in[7];
    const float* a_dst2 = (const float*)d_in[8];
    const float* b2     = (const float*)d_in[9];
    float* out = (float*)d_out;

    const int n = in_sizes[0] / 128;   // 50000
    const int E = 800000;
    const int Etot = E + n;            // 850000
    const int B = 256;

    // CSR build (shared by both layers)
    k_detect<<<1, 32>>>(ei32);
    k_zero_cnt<<<cdiv(n, B), B>>>(n);
    k_build_hist<<<cdiv(Etot, B), B>>>(ei32, E, Etot);
    k_scan1<<<NBLK, SCB>>>(n);
    k_scan2<<<1, 64>>>();
    k_scan3<<<cdiv(n, B), B>>>(n, Etot);
    k_fill<<<cdiv(Etot, B), B>>>(Etot);

    // ---- layer 1 ----
    k_gemm_tiled<128, 64, 1><<<cdiv(n, 128), 256>>>(x, W1, n);
    k_logits<16><<<cdiv((long long)n * NH, B), B>>>(a_src1, a_dst1, n);
    k_agg_csr<1><<<cdiv((long long)n * 32, B), B>>>(b1, nullptr, n);

    // ---- layer 2 ----
    k_gemm_tiled<64, 32, 2><<<cdiv(n, 128), 256>>>(nullptr, W2, n);
    k_logits<8><<<cdiv((long long)n * NH, B), B>>>(a_src2, a_dst2, n);
    k_agg_csr<2><<<cdiv((long long)n * 32, B), B>>>(b2, out, n);
}

// round 9
// speedup vs baseline: 1.7490x; 1.0924x over previous
#include <cuda_runtime.h>
#include <math.h>

#define NN 50000
#define EE 800000
#define ETOT (EE + NN)
#define NH 4
#define NEG 0.2f
#define EPSV 1e-16f
#define SCB 1024
#define NBLK ((NN + SCB - 1) / SCB)   // 49

// ---------------- scratch (device globals; no allocation) ----------------
// NOTE: never pass these as kernel args from host code (host shadow symbol bug).
__device__ float g_h1[NN * 64];     // gemm1 out (NN x 64); later gemm2 out (NN x 32)
__device__ float g_buf[NN * 64];    // layer1 relu'd aggregated features
__device__ float g_als[NN * NH];
__device__ float g_ald[NN * NH];
__device__ int2  g_sd[ETOT];
__device__ int   g_cnt[NN];
__device__ int   g_off[NN + 1];
__device__ int   g_cur[NN];
__device__ int   g_esrc[ETOT];
__device__ int   g_bsum[NBLK];
__device__ int   g_is64;

// ---------------- init: zero degree counts + dtype detect ----------------
__global__ void k_init(const int* __restrict__ ei32, int n) {
    int i = blockIdx.x * blockDim.x + threadIdx.x;
    if (i < n) g_cnt[i] = 0;
    if (i == 0) {
        int all0 = 1;
        for (int j = 0; j < 32; j++)
            if (ei32[2 * j + 1] != 0) { all0 = 0; break; }
        g_is64 = all0;
    }
}

// decode endpoints + dst histogram
__global__ void k_build_hist(const int* __restrict__ ei32, int E, int Etot) {
    int e = blockIdx.x * blockDim.x + threadIdx.x;
    if (e >= Etot) return;
    int s, d;
    if (e < E) {
        if (g_is64) { s = ei32[2 * e]; d = ei32[2 * (E + e)]; }
        else        { s = ei32[e];     d = ei32[E + e]; }
    } else { s = d = e - E; }
    g_sd[e] = make_int2(s, d);
    atomicAdd(&g_cnt[d], 1);
}

// ---------------- multi-block exclusive scan ----------------
__global__ void k_scan1(int n) {
    __shared__ int sh[SCB];
    int t = threadIdx.x;
    int i = blockIdx.x * SCB + t;
    int v = (i < n) ? g_cnt[i] : 0;
    sh[t] = v;
    __syncthreads();
    for (int ofs = 1; ofs < SCB; ofs <<= 1) {
        int u = (t >= ofs) ? sh[t - ofs] : 0;
        __syncthreads();
        sh[t] += u;
        __syncthreads();
    }
    if (i < n) g_off[i] = sh[t] - v;
    if (t == SCB - 1) g_bsum[blockIdx.x] = sh[t];
}

// scan block sums (redundantly per block) + apply + init cursors + sentinel
__global__ void k_scan23(int n, int Etot) {
    __shared__ int sh[NBLK];
    int t = threadIdx.x;
    if (t < NBLK) sh[t] = g_bsum[t];
    __syncthreads();
    if (t == 0) {
        int run = 0;
        for (int j = 0; j < NBLK; j++) { int c = sh[j]; sh[j] = run; run += c; }
    }
    __syncthreads();
    int i = blockIdx.x * blockDim.x + t;
    if (i < n) {
        int o = g_off[i] + sh[i / SCB];
        g_off[i] = o;
        g_cur[i] = o;
    }
    if (i == 0) g_off[n] = Etot;
}

__global__ void k_fill(int Etot) {
    int e = blockIdx.x * blockDim.x + threadIdx.x;
    if (e >= Etot) return;
    int2 sd = g_sd[e];
    int pos = atomicAdd(&g_cur[sd.y], 1);
    g_esrc[pos] = sd.x;
}

// ---------------- tiled GEMM + fused attention-logit epilogue ----------------
// LAYER=1: g_h1 <- x (arg) @ W1  (KTOT=128, COLS=64, KT=64)
// LAYER=2: g_h1 <- g_buf   @ W2  (KTOT=64,  COLS=32, KT=32)
// Epilogue also writes g_als/g_ald = per-head dot(h, a_src/a_dst).
template <int KTOT, int COLS, int LAYER>
__global__ void k_gemm_fused(const float* __restrict__ A_arg,
                             const float* __restrict__ W,
                             const float* __restrict__ asrc,
                             const float* __restrict__ adst, int n) {
    const float* A = (LAYER == 1) ? A_arg : g_buf;
    float* O       = g_h1;
    const int KT  = (KTOT >= 128) ? 64 : 32;
    const int CG  = COLS / 4;       // 16 / 8
    const int TYN = 256 / CG;       // 16 / 32
    const int RPT = 128 / TYN;      // 8 / 4
    const int C   = COLS / NH;      // 16 / 8
    const int TXH = C / 4;          // 4 / 2  (tx lanes per head)
    const int K4  = KT / 4;         // float4s per A row per tile
    __shared__ float As[128][KT + 1];
    __shared__ float Ws[KT][COLS];
    int tid = threadIdx.x;
    int tx = tid % CG, ty = tid / CG;
    int rbase = blockIdx.x * 128;
    float4 acc[RPT];
#pragma unroll
    for (int i = 0; i < RPT; i++) acc[i] = make_float4(0.f, 0.f, 0.f, 0.f);

    for (int kt = 0; kt < KTOT / KT; kt++) {
        int k0 = kt * KT;
        const int ACNT = 128 * K4;            // float4 loads for A tile
#pragma unroll
        for (int j = 0; j < ACNT / 256; j++) {
            int idx = tid + j * 256;
            int row = idx / K4, k4 = idx % K4;
            int rg = rbase + row;
            if (rg >= n) rg = n - 1;
            float4 v = *reinterpret_cast<const float4*>(&A[rg * KTOT + k0 + k4 * 4]);
            As[row][k4 * 4 + 0] = v.x;
            As[row][k4 * 4 + 1] = v.y;
            As[row][k4 * 4 + 2] = v.z;
            As[row][k4 * 4 + 3] = v.w;
        }
        const int WCNT = KT * COLS / 4;
#pragma unroll
        for (int j = 0; j < (WCNT + 255) / 256; j++) {
            int idx = tid + j * 256;
            if (idx < WCNT) {
                int k = idx / CG, c4 = idx % CG;
                *reinterpret_cast<float4*>(&Ws[k][c4 * 4]) =
                    *reinterpret_cast<const float4*>(&W[(k0 + k) * COLS + c4 * 4]);
            }
        }
        __syncthreads();
#pragma unroll
        for (int kk = 0; kk < KT; kk++) {
            float4 b = *reinterpret_cast<const float4*>(&Ws[kk][tx * 4]);
#pragma unroll
            for (int i = 0; i < RPT; i++) {
                float a = As[ty * RPT + i][kk];
                acc[i].x = fmaf(a, b.x, acc[i].x);
                acc[i].y = fmaf(a, b.y, acc[i].y);
                acc[i].z = fmaf(a, b.z, acc[i].z);
                acc[i].w = fmaf(a, b.w, acc[i].w);
            }
        }
        __syncthreads();
    }
    // epilogue: store rows + fused per-head logits
    float4 sa = *reinterpret_cast<const float4*>(&asrc[tx * 4]);
    float4 da = *reinterpret_cast<const float4*>(&adst[tx * 4]);
    int h = tx / TXH;
#pragma unroll
    for (int i = 0; i < RPT; i++) {
        int r = rbase + ty * RPT + i;
        float ps = acc[i].x * sa.x + acc[i].y * sa.y + acc[i].z * sa.z + acc[i].w * sa.w;
        float pd = acc[i].x * da.x + acc[i].y * da.y + acc[i].z * da.z + acc[i].w * da.w;
#pragma unroll
        for (int ofs = 1; ofs < TXH; ofs <<= 1) {
            ps += __shfl_xor_sync(0xffffffffu, ps, ofs);
            pd += __shfl_xor_sync(0xffffffffu, pd, ofs);
        }
        if (r < n) {
            *reinterpret_cast<float4*>(&O[r * COLS + tx * 4]) = acc[i];
            if ((tx & (TXH - 1)) == 0) {
                g_als[r * 4 + h] = ps;
                g_ald[r * 4 + h] = pd;
            }
        }
    }
}

// ---------------- CSR aggregation: one warp per dst node ----------------
// LAYER=1: gather g_h1 (HC=64), epilogue relu(acc/sum + b1) -> g_buf
// LAYER=2: gather g_h1 (HC=32), epilogue log_softmax(acc/sum + b2) -> out (arg)
template <int LAYER>
__global__ void k_agg_csr(const float* __restrict__ bias, float* __restrict__ out_arg, int n) {
    const int HC   = (LAYER == 1) ? 64 : 32;
    const int C    = HC / NH;
    const int LPE  = HC / 4;
    const int SUBS = 32 / LPE;
    int warp = (blockIdx.x * blockDim.x + threadIdx.x) >> 5;
    if (warp >= n) return;
    int d = warp;
    int lane = threadIdx.x & 31;
    int sub = lane / LPE;
    int l = lane % LPE;
    int h = (l * 4) / C;
    float ald_v = g_ald[d * 4 + h];
    int off0 = g_off[d], off1 = g_off[d + 1];
    float4 acc = make_float4(0.f, 0.f, 0.f, 0.f);
    float esum = 0.f;
    for (int i = off0 + sub; i < off1; i += SUBS) {
        int s = g_esrc[i];
        float lg = g_als[s * 4 + h] + ald_v;
        lg = (lg >= 0.f) ? lg : NEG * lg;
        float ev = __expf(lg);
        esum += ev;
        float4 v = *reinterpret_cast<const float4*>(&g_h1[s * HC + l * 4]);
        acc.x = fmaf(ev, v.x, acc.x);
        acc.y = fmaf(ev, v.y, acc.y);
        acc.z = fmaf(ev, v.z, acc.z);
        acc.w = fmaf(ev, v.w, acc.w);
    }
#pragma unroll
    for (int ofs = LPE; ofs < 32; ofs <<= 1) {
        acc.x += __shfl_xor_sync(0xffffffffu, acc.x, ofs);
        acc.y += __shfl_xor_sync(0xffffffffu, acc.y, ofs);
        acc.z += __shfl_xor_sync(0xffffffffu, acc.z, ofs);
        acc.w += __shfl_xor_sync(0xffffffffu, acc.w, ofs);
        esum  += __shfl_xor_sync(0xffffffffu, esum, ofs);
    }
    float inv = 1.f / (esum + EPSV);
    float4 b = reinterpret_cast<const float4*>(bias)[l];
    float4 r;
    r.x = fmaf(acc.x, inv, b.x);
    r.y = fmaf(acc.y, inv, b.y);
    r.z = fmaf(acc.z, inv, b.z);
    r.w = fmaf(acc.w, inv, b.w);
    if (LAYER == 1) {
        r.x = fmaxf(r.x, 0.f); r.y = fmaxf(r.y, 0.f);
        r.z = fmaxf(r.z, 0.f); r.w = fmaxf(r.w, 0.f);
        if (sub == 0)
            *reinterpret_cast<float4*>(&g_buf[d * 64 + l * 4]) = r;
    } else {
        float m = fmaxf(fmaxf(r.x, r.y), fmaxf(r.z, r.w));
#pragma unroll
        for (int ofs = 1; ofs < 8; ofs <<= 1)
            m = fmaxf(m, __shfl_xor_sync(0xffffffffu, m, ofs));
        float ssum = expf(r.x - m) + expf(r.y - m) + expf(r.z - m) + expf(r.w - m);
#pragma unroll
        for (int ofs = 1; ofs < 8; ofs <<= 1)
            ssum += __shfl_xor_sync(0xffffffffu, ssum, ofs);
        float ls = m + logf(ssum);
        r.x -= ls; r.y -= ls; r.z -= ls; r.w -= ls;
        if (sub == 0)
            *reinterpret_cast<float4*>(&out_arg[d * 32 + l * 4]) = r;
    }
}

// ---------------- launch ----------------
static inline int cdiv(long long a, int b) { return (int)((a + b - 1) / b); }

extern "C" void kernel_launch(void* const* d_in, const int* in_sizes, int n_in,
                              void* d_out, int out_size) {
    const float* x      = (const float*)d_in[0];
    const int*   ei32   = (const int*)d_in[1];
    const float* W1     = (const float*)d_in[2];
    const float* a_src1 = (const float*)d_in[3];
    const float* a_dst1 = (const float*)d_in[4];
    const float* b1     = (const float*)d_in[5];
    const float* W2     = (const float*)d_in[6];
    const float* a_src2 = (const float*)d_in[7];
    const float* a_dst2 = (const float*)d_in[8];
    const float* b2     = (const float*)d_in[9];
    float* out = (float*)d_out;

    const int n = in_sizes[0] / 128;   // 50000
    const int E = 800000;
    const int Etot = E + n;            // 850000
    const int B = 256;

    // CSR build (shared by both layers)
    k_init<<<cdiv(n, B), B>>>(ei32, n);
    k_build_hist<<<cdiv(Etot, B), B>>>(ei32, E, Etot);
    k_scan1<<<NBLK, SCB>>>(n);
    k_scan23<<<cdiv(n, B), B>>>(n, Etot);
    k_fill<<<cdiv(Etot, B), B>>>(Etot);

    // ---- layer 1 ----
    k_gemm_fused<128, 64, 1><<<cdiv(n, 128), 256>>>(x, W1, a_src1, a_dst1, n);
    k_agg_csr<1><<<cdiv((long long)n * 32, B), B>>>(b1, nullptr, n);

    // ---- layer 2 ----
    k_gemm_fused<64, 32, 2><<<cdiv(n, 128), 256>>>(nullptr, W2, a_src2, a_dst2, n);
    k_agg_csr<2><<<cdiv((long long)n * 32, B), B>>>(b2, out, n);
}

// round 10
// speedup vs baseline: 1.7826x; 1.0192x over previous
#include <cuda_runtime.h>
#include <cuda_fp16.h>
#include <math.h>

#define NN 50000
#define EE 800000
#define ETOT (EE + NN)
#define NH 4
#define NEG 0.2f
#define EPSV 1e-16f
#define SCB 1024
#define NBLK ((NN + SCB - 1) / SCB)   // 49

// ---------------- scratch (device globals; no allocation) ----------------
// NOTE: never pass these as kernel args from host code (host shadow symbol bug).
__device__ __half g_h1h[NN * 64];   // gemm out in fp16 (gather-only buffer)
__device__ float  g_buf[NN * 64];   // layer1 relu'd aggregated features (fp32)
__device__ float  g_als[NN * NH];
__device__ float  g_ald[NN * NH];
__device__ int    g_cnt[NN];
__device__ int    g_off[NN + 1];
__device__ int    g_cur[NN];
__device__ int    g_esrc[ETOT];
__device__ int    g_bsum[NBLK];
__device__ int    g_is64;

// ---------------- init: zero degree counts + dtype detect ----------------
__global__ void k_init(const int* __restrict__ ei32, int n) {
    int i = blockIdx.x * blockDim.x + threadIdx.x;
    if (i < n) g_cnt[i] = 0;
    if (i == 0) {
        int all0 = 1;
        for (int j = 0; j < 32; j++)
            if (ei32[2 * j + 1] != 0) { all0 = 0; break; }
        g_is64 = all0;
    }
}

// dst histogram (decode dst only)
__global__ void k_build_hist(const int* __restrict__ ei32, int E, int Etot) {
    int e = blockIdx.x * blockDim.x + threadIdx.x;
    if (e >= Etot) return;
    int d;
    if (e < E) d = g_is64 ? ei32[2 * (E + e)] : ei32[E + e];
    else       d = e - E;
    atomicAdd(&g_cnt[d], 1);
}

// ---------------- shfl-based multi-block exclusive scan ----------------
__global__ void k_scan1(int n) {
    __shared__ int ws[32];
    int t = threadIdx.x;
    int i = blockIdx.x * SCB + t;
    int v = (i < n) ? g_cnt[i] : 0;
    int x = v;
#pragma unroll
    for (int ofs = 1; ofs < 32; ofs <<= 1) {
        int u = __shfl_up_sync(0xffffffffu, x, ofs);
        if ((t & 31) >= ofs) x += u;
    }
    if ((t & 31) == 31) ws[t >> 5] = x;
    __syncthreads();
    if (t < 32) {
        int y = ws[t];
#pragma unroll
        for (int ofs = 1; ofs < 32; ofs <<= 1) {
            int u = __shfl_up_sync(0xffffffffu, y, ofs);
            if (t >= ofs) y += u;
        }
        ws[t] = y;                       // inclusive warp-sum prefix
    }
    __syncthreads();
    int base = (t >= 32) ? ws[(t >> 5) - 1] : 0;
    int incl = x + base;
    if (i < n) g_off[i] = incl - v;      // block-local exclusive
    if (t == SCB - 1) g_bsum[blockIdx.x] = incl;
}

// scan block sums (2-warp shfl, redundantly per block) + apply + cursors + sentinel
__global__ void k_scan23(int n, int Etot) {
    __shared__ int sh[64];
    __shared__ int tot0;
    int t = threadIdx.x;
    if (t < 64) {
        int v = (t < NBLK) ? g_bsum[t] : 0;
        int x = v;
#pragma unroll
        for (int ofs = 1; ofs < 32; ofs <<= 1) {
            int u = __shfl_up_sync(0xffffffffu, x, ofs);
            if ((t & 31) >= ofs) x += u;
        }
        sh[t] = x - v;                   // warp-local exclusive
        if (t == 31) tot0 = x;           // warp0 total
    }
    __syncthreads();
    if (t >= 32 && t < 64) sh[t] += tot0;
    __syncthreads();
    int i = blockIdx.x * blockDim.x + t;
    if (i < n) {
        int o = g_off[i] + sh[i / SCB];
        g_off[i] = o;
        g_cur[i] = o;
    }
    if (i == 0) g_off[n] = Etot;
}

// bucket-fill: src ids grouped by dst (re-reads ei32 directly)
__global__ void k_fill(const int* __restrict__ ei32, int E, int Etot) {
    int e = blockIdx.x * blockDim.x + threadIdx.x;
    if (e >= Etot) return;
    int s, d;
    if (e < E) {
        if (g_is64) { s = ei32[2 * e]; d = ei32[2 * (E + e)]; }
        else        { s = ei32[e];     d = ei32[E + e]; }
    } else { s = d = e - E; }
    int pos = atomicAdd(&g_cur[d], 1);
    g_esrc[pos] = s;
}

// ---------------- tiled GEMM + fused logits, fp16 feature output ----------------
// LAYER=1: g_h1h <- fp16(x @ W1)    (KTOT=128, COLS=64, KT=64)
// LAYER=2: g_h1h <- fp16(g_buf @ W2)(KTOT=64,  COLS=32, KT=32)
// Also writes fp32 g_als/g_ald = per-head dot(h, a_src/a_dst).
template <int KTOT, int COLS, int LAYER>
__global__ void k_gemm_fused(const float* __restrict__ A_arg,
                             const float* __restrict__ W,
                             const float* __restrict__ asrc,
                             const float* __restrict__ adst, int n) {
    const float* A = (LAYER == 1) ? A_arg : g_buf;
    const int KT  = (KTOT >= 128) ? 64 : 32;
    const int CG  = COLS / 4;
    const int TYN = 256 / CG;
    const int RPT = 128 / TYN;
    const int C   = COLS / NH;
    const int TXH = C / 4;
    const int K4  = KT / 4;
    __shared__ float As[128][KT + 1];
    __shared__ float Ws[KT][COLS];
    int tid = threadIdx.x;
    int tx = tid % CG, ty = tid / CG;
    int rbase = blockIdx.x * 128;
    float4 acc[RPT];
#pragma unroll
    for (int i = 0; i < RPT; i++) acc[i] = make_float4(0.f, 0.f, 0.f, 0.f);

    for (int kt = 0; kt < KTOT / KT; kt++) {
        int k0 = kt * KT;
        const int ACNT = 128 * K4;
#pragma unroll
        for (int j = 0; j < ACNT / 256; j++) {
            int idx = tid + j * 256;
            int row = idx / K4, k4 = idx % K4;
            int rg = rbase + row;
            if (rg >= n) rg = n - 1;
            float4 v = *reinterpret_cast<const float4*>(&A[rg * KTOT + k0 + k4 * 4]);
            As[row][k4 * 4 + 0] = v.x;
            As[row][k4 * 4 + 1] = v.y;
            As[row][k4 * 4 + 2] = v.z;
            As[row][k4 * 4 + 3] = v.w;
        }
        const int WCNT = KT * COLS / 4;
#pragma unroll
        for (int j = 0; j < (WCNT + 255) / 256; j++) {
            int idx = tid + j * 256;
            if (idx < WCNT) {
                int k = idx / CG, c4 = idx % CG;
                *reinterpret_cast<float4*>(&Ws[k][c4 * 4]) =
                    *reinterpret_cast<const float4*>(&W[(k0 + k) * COLS + c4 * 4]);
            }
        }
        __syncthreads();
#pragma unroll
        for (int kk = 0; kk < KT; kk++) {
            float4 b = *reinterpret_cast<const float4*>(&Ws[kk][tx * 4]);
#pragma unroll
            for (int i = 0; i < RPT; i++) {
                float a = As[ty * RPT + i][kk];
                acc[i].x = fmaf(a, b.x, acc[i].x);
                acc[i].y = fmaf(a, b.y, acc[i].y);
                acc[i].z = fmaf(a, b.z, acc[i].z);
                acc[i].w = fmaf(a, b.w, acc[i].w);
            }
        }
        __syncthreads();
    }
    float4 sa = *reinterpret_cast<const float4*>(&asrc[tx * 4]);
    float4 da = *reinterpret_cast<const float4*>(&adst[tx * 4]);
    int h = tx / TXH;
#pragma unroll
    for (int i = 0; i < RPT; i++) {
        int r = rbase + ty * RPT + i;
        float ps = acc[i].x * sa.x + acc[i].y * sa.y + acc[i].z * sa.z + acc[i].w * sa.w;
        float pd = acc[i].x * da.x + acc[i].y * da.y + acc[i].z * da.z + acc[i].w * da.w;
#pragma unroll
        for (int ofs = 1; ofs < TXH; ofs <<= 1) {
            ps += __shfl_xor_sync(0xffffffffu, ps, ofs);
            pd += __shfl_xor_sync(0xffffffffu, pd, ofs);
        }
        if (r < n) {
            __half2 ha = __floats2half2_rn(acc[i].x, acc[i].y);
            __half2 hb = __floats2half2_rn(acc[i].z, acc[i].w);
            uint2 u;
            u.x = *reinterpret_cast<unsigned*>(&ha);
            u.y = *reinterpret_cast<unsigned*>(&hb);
            *reinterpret_cast<uint2*>(&g_h1h[r * COLS + tx * 4]) = u;
            if ((tx & (TXH - 1)) == 0) {
                g_als[r * 4 + h] = ps;
                g_ald[r * 4 + h] = pd;
            }
        }
    }
}

// ---------------- CSR aggregation: one warp per dst node, fp16 gather ----------------
// Each lane covers 8 channels (16B). LAYER=1: HC=64, LPE=8, SUBS=4 -> relu -> g_buf.
// LAYER=2: HC=32, LPE=4, SUBS=8 -> log_softmax -> out (arg).
template <int LAYER>
__global__ void k_agg_csr(const float* __restrict__ bias, float* __restrict__ out_arg, int n) {
    const int HC   = (LAYER == 1) ? 64 : 32;
    const int C    = HC / NH;          // 16 / 8
    const int LPE  = HC / 8;           // 8 / 4 lanes per edge
    const int SUBS = 32 / LPE;         // 4 / 8 edges in flight
    int warp = (blockIdx.x * blockDim.x + threadIdx.x) >> 5;
    if (warp >= n) return;
    int d = warp;
    int lane = threadIdx.x & 31;
    int sub = lane / LPE;
    int l = lane % LPE;
    int h = (l * 8) / C;               // l/2 (L1), l (L2)
    float ald_v = g_ald[d * 4 + h];
    int off0 = g_off[d], off1 = g_off[d + 1];
    float a0 = 0.f, a1 = 0.f, a2 = 0.f, a3 = 0.f;
    float a4 = 0.f, a5 = 0.f, a6 = 0.f, a7 = 0.f;
    float esum = 0.f;
    for (int i = off0 + sub; i < off1; i += SUBS) {
        int s = g_esrc[i];
        float lg = g_als[s * 4 + h] + ald_v;
        lg = (lg >= 0.f) ? lg : NEG * lg;
        float ev = __expf(lg);
        esum += ev;
        uint4 raw = *reinterpret_cast<const uint4*>(&g_h1h[s * HC + l * 8]);
        float2 f0 = __half22float2(*reinterpret_cast<__half2*>(&raw.x));
        float2 f1 = __half22float2(*reinterpret_cast<__half2*>(&raw.y));
        float2 f2 = __half22float2(*reinterpret_cast<__half2*>(&raw.z));
        float2 f3 = __half22float2(*reinterpret_cast<__half2*>(&raw.w));
        a0 = fmaf(ev, f0.x, a0); a1 = fmaf(ev, f0.y, a1);
        a2 = fmaf(ev, f1.x, a2); a3 = fmaf(ev, f1.y, a3);
        a4 = fmaf(ev, f2.x, a4); a5 = fmaf(ev, f2.y, a5);
        a6 = fmaf(ev, f3.x, a6); a7 = fmaf(ev, f3.y, a7);
    }
#pragma unroll
    for (int ofs = LPE; ofs < 32; ofs <<= 1) {
        a0 += __shfl_xor_sync(0xffffffffu, a0, ofs);
        a1 += __shfl_xor_sync(0xffffffffu, a1, ofs);
        a2 += __shfl_xor_sync(0xffffffffu, a2, ofs);
        a3 += __shfl_xor_sync(0xffffffffu, a3, ofs);
        a4 += __shfl_xor_sync(0xffffffffu, a4, ofs);
        a5 += __shfl_xor_sync(0xffffffffu, a5, ofs);
        a6 += __shfl_xor_sync(0xffffffffu, a6, ofs);
        a7 += __shfl_xor_sync(0xffffffffu, a7, ofs);
        esum += __shfl_xor_sync(0xffffffffu, esum, ofs);
    }
    float inv = 1.f / (esum + EPSV);
    float4 b0 = reinterpret_cast<const float4*>(bias)[l * 2];
    float4 b1v = reinterpret_cast<const float4*>(bias)[l * 2 + 1];
    float r0 = fmaf(a0, inv, b0.x), r1 = fmaf(a1, inv, b0.y);
    float r2 = fmaf(a2, inv, b0.z), r3 = fmaf(a3, inv, b0.w);
    float r4 = fmaf(a4, inv, b1v.x), r5 = fmaf(a5, inv, b1v.y);
    float r6 = fmaf(a6, inv, b1v.z), r7 = fmaf(a7, inv, b1v.w);
    if (LAYER == 1) {
        if (sub == 0) {
            float4 o0 = make_float4(fmaxf(r0, 0.f), fmaxf(r1, 0.f), fmaxf(r2, 0.f), fmaxf(r3, 0.f));
            float4 o1 = make_float4(fmaxf(r4, 0.f), fmaxf(r5, 0.f), fmaxf(r6, 0.f), fmaxf(r7, 0.f));
            *reinterpret_cast<float4*>(&g_buf[d * 64 + l * 8]) = o0;
            *reinterpret_cast<float4*>(&g_buf[d * 64 + l * 8 + 4]) = o1;
        }
    } else {
        // log_softmax over 32 channels spread across LPE=4 lanes x 8 each
        float m = fmaxf(fmaxf(fmaxf(r0, r1), fmaxf(r2, r3)),
                        fmaxf(fmaxf(r4, r5), fmaxf(r6, r7)));
#pragma unroll
        for (int ofs = 1; ofs < LPE; ofs <<= 1)
            m = fmaxf(m, __shfl_xor_sync(0xffffffffu, m, ofs));
        float ssum = expf(r0 - m) + expf(r1 - m) + expf(r2 - m) + expf(r3 - m)
                   + expf(r4 - m) + expf(r5 - m) + expf(r6 - m) + expf(r7 - m);
#pragma unroll
        for (int ofs = 1; ofs < LPE; ofs <<= 1)
            ssum += __shfl_xor_sync(0xffffffffu, ssum, ofs);
        float ls = m + logf(ssum);
        if (sub == 0) {
            float4 o0 = make_float4(r0 - ls, r1 - ls, r2 - ls, r3 - ls);
            float4 o1 = make_float4(r4 - ls, r5 - ls, r6 - ls, r7 - ls);
            *reinterpret_cast<float4*>(&out_arg[d * 32 + l * 8]) = o0;
            *reinterpret_cast<float4*>(&out_arg[d * 32 + l * 8 + 4]) = o1;
        }
    }
}

// ---------------- launch ----------------
static inline int cdiv(long long a, int b) { return (int)((a + b - 1) / b); }

extern "C" void kernel_launch(void* const* d_in, const int* in_sizes, int n_in,
                              void* d_out, int out_size) {
    const float* x      = (const float*)d_in[0];
    const int*   ei32   = (const int*)d_in[1];
    const float* W1     = (const float*)d_in[2];
    const float* a_src1 = (const float*)d_in[3];
    const float* a_dst1 = (const float*)d_in[4];
    const float* b1     = (const float*)d_in[5];
    const float* W2     = (const float*)d_in[6];
    const float* a_src2 = (const float*)d_in[7];
    const float* a_dst2 = (const float*)d_in[8];
    const float* b2     = (const float*)d_in[9];
    float* out = (float*)d_out;

    const int n = in_sizes[0] / 128;   // 50000
    const int E = 800000;
    const int Etot = E + n;            // 850000
    const int B = 256;

    // CSR build (shared by both layers)
    k_init<<<cdiv(n, B), B>>>(ei32, n);
    k_build_hist<<<cdiv(Etot, B), B>>>(ei32, E, Etot);
    k_scan1<<<NBLK, SCB>>>(n);
    k_scan23<<<cdiv(n, B), B>>>(n, Etot);
    k_fill<<<cdiv(Etot, B), B>>>(ei32, E, Etot);

    // ---- layer 1 ----
    k_gemm_fused<128, 64, 1><<<cdiv(n, 128), 256>>>(x, W1, a_src1, a_dst1, n);
    k_agg_csr<1><<<cdiv((long long)n * 32, B), B>>>(b1, nullptr, n);

    // ---- layer 2 ----
    k_gemm_fused<64, 32, 2><<<cdiv(n, 128), 256>>>(nullptr, W2, a_src2, a_dst2, n);
    k_agg_csr<2><<<cdiv((long long)n * 32, B), B>>>(b2, out, n);
}

// round 11
// speedup vs baseline: 2.2098x; 1.2396x over previous
#include <cuda_runtime.h>
#include <cuda_fp16.h>
#include <mma.h>
#include <math.h>

using namespace nvcuda;

#define NN 50000
#define EE 800000
#define ETOT (EE + NN)
#define NH 4
#define NEG 0.2f
#define EPSV 1e-16f
#define SCB 1024
#define NBLK ((NN + SCB - 1) / SCB)   // 49

// ---------------- scratch (device globals; no allocation) ----------------
// NOTE: never pass these as kernel args from host code (host shadow symbol bug).
__device__ __half g_h1h[NN * 64];   // gemm out in fp16 (gather-only buffer)
__device__ float  g_buf[NN * 64];   // layer1 relu'd aggregated features (fp32)
__device__ float  g_als[NN * NH];
__device__ float  g_ald[NN * NH];
__device__ int    g_cnt[NN];        // zeroed at program start; re-zeroed by k_scan23
__device__ int    g_off[NN + 1];
__device__ int    g_cur[NN];
__device__ int    g_esrc[ETOT];
__device__ int    g_bsum[NBLK];
__device__ int    g_is64;

// ---------------- dtype detect (1 warp) ----------------
__global__ void k_detect(const int* __restrict__ ei32) {
    if (threadIdx.x == 0) {
        int all0 = 1;
        for (int j = 0; j < 32; j++)
            if (ei32[2 * j + 1] != 0) { all0 = 0; break; }
        g_is64 = all0;
    }
}

// dst histogram (g_cnt starts zeroed: initial static init, then k_scan23 re-zeros)
__global__ void k_build_hist(const int* __restrict__ ei32, int E, int Etot) {
    int e = blockIdx.x * blockDim.x + threadIdx.x;
    if (e >= Etot) return;
    int d;
    if (e < E) d = g_is64 ? ei32[2 * (E + e)] : ei32[E + e];
    else       d = e - E;
    atomicAdd(&g_cnt[d], 1);
}

// ---------------- shfl-based multi-block exclusive scan ----------------
__global__ void k_scan1(int n) {
    __shared__ int ws[32];
    int t = threadIdx.x;
    int i = blockIdx.x * SCB + t;
    int v = (i < n) ? g_cnt[i] : 0;
    int x = v;
#pragma unroll
    for (int ofs = 1; ofs < 32; ofs <<= 1) {
        int u = __shfl_up_sync(0xffffffffu, x, ofs);
        if ((t & 31) >= ofs) x += u;
    }
    if ((t & 31) == 31) ws[t >> 5] = x;
    __syncthreads();
    if (t < 32) {
        int y = ws[t];
#pragma unroll
        for (int ofs = 1; ofs < 32; ofs <<= 1) {
            int u = __shfl_up_sync(0xffffffffu, y, ofs);
            if (t >= ofs) y += u;
        }
        ws[t] = y;
    }
    __syncthreads();
    int base = (t >= 32) ? ws[(t >> 5) - 1] : 0;
    int incl = x + base;
    if (i < n) g_off[i] = incl - v;
    if (t == SCB - 1) g_bsum[blockIdx.x] = incl;
}

// scan block sums + apply + cursors + sentinel + re-zero g_cnt (replay invariant)
__global__ void k_scan23(int n, int Etot) {
    __shared__ int sh[64];
    __shared__ int tot0;
    int t = threadIdx.x;
    if (t < 64) {
        int v = (t < NBLK) ? g_bsum[t] : 0;
        int x = v;
#pragma unroll
        for (int ofs = 1; ofs < 32; ofs <<= 1) {
            int u = __shfl_up_sync(0xffffffffu, x, ofs);
            if ((t & 31) >= ofs) x += u;
        }
        sh[t] = x - v;
        if (t == 31) tot0 = x;
    }
    __syncthreads();
    if (t >= 32 && t < 64) sh[t] += tot0;
    __syncthreads();
    int i = blockIdx.x * blockDim.x + t;
    if (i < n) {
        int o = g_off[i] + sh[i / SCB];
        g_off[i] = o;
        g_cur[i] = o;
        g_cnt[i] = 0;            // restore for next launch/replay
    }
    if (i == 0) g_off[n] = Etot;
}

// bucket-fill: src ids grouped by dst
__global__ void k_fill(const int* __restrict__ ei32, int E, int Etot) {
    int e = blockIdx.x * blockDim.x + threadIdx.x;
    if (e >= Etot) return;
    int s, d;
    if (e < E) {
        if (g_is64) { s = ei32[2 * e]; d = ei32[2 * (E + e)]; }
        else        { s = ei32[e];     d = ei32[E + e]; }
    } else { s = d = e - E; }
    int pos = atomicAdd(&g_cur[d], 1);
    g_esrc[pos] = s;
}

// ---------------- wmma fp16 GEMM + fused logits, fp16 feature output ----------------
// LAYER=1: g_h1h <- fp16(x @ W1)     KTOT=128, COLS=64. LAYER=2: g_h1h <- fp16(g_buf @ W2) KTOT=64, COLS=32.
// Block: 64 rows x COLS, 128 threads (4 warps, each warp 16 rows x COLS).
// Also writes fp32 g_als/g_ald = per-head dot(h, a_src/a_dst).
template <int KTOT, int COLS, int LAYER>
__global__ void k_gemm_wmma(const float* __restrict__ A_arg,
                            const float* __restrict__ W,
                            const float* __restrict__ asrc,
                            const float* __restrict__ adst, int n) {
    const float* A = (LAYER == 1) ? A_arg : g_buf;
    const int LDA = KTOT + 8;          // half stride (mult of 8)
    const int LDB = COLS + 8;          // half stride
    const int LDC = COLS + 8;          // float stride (mult of 4)
    const int NF  = COLS / 16;         // c-fragments per warp (4 / 2)
    // smem: phase A = [As | Bs], phase C overlays from offset 0
    __shared__ __align__(16) char sraw[64 * (KTOT + 8) * 2 + KTOT * (COLS + 8) * 2 >
                                       64 * (COLS + 8) * 4
                                       ? 64 * (KTOT + 8) * 2 + KTOT * (COLS + 8) * 2
                                       : 64 * (COLS + 8) * 4];
    __half* As = reinterpret_cast<__half*>(sraw);
    __half* Bs = reinterpret_cast<__half*>(sraw + 64 * LDA * 2);
    float*  Cs = reinterpret_cast<float*>(sraw);

    int tid = threadIdx.x;
    int w = tid >> 5;
    int rbase = blockIdx.x * 64;

    // load A tile (64 x KTOT) fp32 -> fp16
    const int A4 = 64 * KTOT / 4;
#pragma unroll
    for (int j = 0; j < A4 / 128; j++) {
        int idx = tid + j * 128;
        int row = idx / (KTOT / 4), k4 = idx % (KTOT / 4);
        int rg = rbase + row;
        if (rg >= n) rg = n - 1;
        float4 v = *reinterpret_cast<const float4*>(&A[rg * KTOT + k4 * 4]);
        __half2 h0 = __floats2half2_rn(v.x, v.y);
        __half2 h1 = __floats2half2_rn(v.z, v.w);
        uint2 u;
        u.x = *reinterpret_cast<unsigned*>(&h0);
        u.y = *reinterpret_cast<unsigned*>(&h1);
        *reinterpret_cast<uint2*>(&As[row * LDA + k4 * 4]) = u;
    }
    // load B tile (KTOT x COLS) fp32 -> fp16
    const int B4 = KTOT * COLS / 4;
#pragma unroll
    for (int j = 0; j < B4 / 128; j++) {
        int idx = tid + j * 128;
        int row = idx / (COLS / 4), c4 = idx % (COLS / 4);
        float4 v = *reinterpret_cast<const float4*>(&W[row * COLS + c4 * 4]);
        __half2 h0 = __floats2half2_rn(v.x, v.y);
        __half2 h1 = __floats2half2_rn(v.z, v.w);
        uint2 u;
        u.x = *reinterpret_cast<unsigned*>(&h0);
        u.y = *reinterpret_cast<unsigned*>(&h1);
        *reinterpret_cast<uint2*>(&Bs[row * LDB + c4 * 4]) = u;
    }
    __syncthreads();

    wmma::fragment<wmma::accumulator, 16, 16, 16, float> c[NF];
#pragma unroll
    for (int j = 0; j < NF; j++) wmma::fill_fragment(c[j], 0.f);
#pragma unroll
    for (int k0 = 0; k0 < KTOT; k0 += 16) {
        wmma::fragment<wmma::matrix_a, 16, 16, 16, __half, wmma::row_major> a;
        wmma::load_matrix_sync(a, &As[w * 16 * LDA + k0], LDA);
#pragma unroll
        for (int j = 0; j < NF; j++) {
            wmma::fragment<wmma::matrix_b, 16, 16, 16, __half, wmma::row_major> b;
            wmma::load_matrix_sync(b, &Bs[k0 * LDB + j * 16], LDB);
            wmma::mma_sync(c[j], a, b, c[j]);
        }
    }
    __syncthreads();                    // all fragment loads done -> safe to overlay
#pragma unroll
    for (int j = 0; j < NF; j++)
        wmma::store_matrix_sync(&Cs[w * 16 * LDC + j * 16], c[j], LDC, wmma::mem_row_major);
    __syncthreads();

    // epilogue: read rows from Cs, fused per-head logits, fp16 store
    const int CG  = COLS / 4;           // 16 / 8
    const int RPT = 64 * CG / 128;      // 8 / 4 rows per thread
    const int C   = COLS / NH;          // 16 / 8
    const int TXH = C / 4;              // 4 / 2
    int tx = tid % CG, ty = tid / CG;
    float4 sa = *reinterpret_cast<const float4*>(&asrc[tx * 4]);
    float4 da = *reinterpret_cast<const float4*>(&adst[tx * 4]);
    int h = tx / TXH;
#pragma unroll
    for (int i = 0; i < RPT; i++) {
        int row = ty * RPT + i;
        int r = rbase + row;
        float4 acc = *reinterpret_cast<const float4*>(&Cs[row * LDC + tx * 4]);
        float ps = acc.x * sa.x + acc.y * sa.y + acc.z * sa.z + acc.w * sa.w;
        float pd = acc.x * da.x + acc.y * da.y + acc.z * da.z + acc.w * da.w;
#pragma unroll
        for (int ofs = 1; ofs < TXH; ofs <<= 1) {
            ps += __shfl_xor_sync(0xffffffffu, ps, ofs);
            pd += __shfl_xor_sync(0xffffffffu, pd, ofs);
        }
        if (r < n) {
            __half2 ha = __floats2half2_rn(acc.x, acc.y);
            __half2 hb = __floats2half2_rn(acc.z, acc.w);
            uint2 u;
            u.x = *reinterpret_cast<unsigned*>(&ha);
            u.y = *reinterpret_cast<unsigned*>(&hb);
            *reinterpret_cast<uint2*>(&g_h1h[r * COLS + tx * 4]) = u;
            if ((tx & (TXH - 1)) == 0) {
                g_als[r * 4 + h] = ps;
                g_ald[r * 4 + h] = pd;
            }
        }
    }
}

// ---------------- CSR aggregation: one warp per dst node, fp16 gather ----------------
template <int LAYER>
__global__ void k_agg_csr(const float* __restrict__ bias, float* __restrict__ out_arg, int n) {
    const int HC   = (LAYER == 1) ? 64 : 32;
    const int C    = HC / NH;
    const int LPE  = HC / 8;
    const int SUBS = 32 / LPE;
    int warp = (blockIdx.x * blockDim.x + threadIdx.x) >> 5;
    if (warp >= n) return;
    int d = warp;
    int lane = threadIdx.x & 31;
    int sub = lane / LPE;
    int l = lane % LPE;
    int h = (l * 8) / C;
    float ald_v = g_ald[d * 4 + h];
    int off0 = g_off[d], off1 = g_off[d + 1];
    float a0 = 0.f, a1 = 0.f, a2 = 0.f, a3 = 0.f;
    float a4 = 0.f, a5 = 0.f, a6 = 0.f, a7 = 0.f;
    float esum = 0.f;
    for (int i = off0 + sub; i < off1; i += SUBS) {
        int s = g_esrc[i];
        float lg = g_als[s * 4 + h] + ald_v;
        lg = (lg >= 0.f) ? lg : NEG * lg;
        float ev = __expf(lg);
        esum += ev;
        uint4 raw = *reinterpret_cast<const uint4*>(&g_h1h[s * HC + l * 8]);
        float2 f0 = __half22float2(*reinterpret_cast<__half2*>(&raw.x));
        float2 f1 = __half22float2(*reinterpret_cast<__half2*>(&raw.y));
        float2 f2 = __half22float2(*reinterpret_cast<__half2*>(&raw.z));
        float2 f3 = __half22float2(*reinterpret_cast<__half2*>(&raw.w));
        a0 = fmaf(ev, f0.x, a0); a1 = fmaf(ev, f0.y, a1);
        a2 = fmaf(ev, f1.x, a2); a3 = fmaf(ev, f1.y, a3);
        a4 = fmaf(ev, f2.x, a4); a5 = fmaf(ev, f2.y, a5);
        a6 = fmaf(ev, f3.x, a6); a7 = fmaf(ev, f3.y, a7);
    }
#pragma unroll
    for (int ofs = LPE; ofs < 32; ofs <<= 1) {
        a0 += __shfl_xor_sync(0xffffffffu, a0, ofs);
        a1 += __shfl_xor_sync(0xffffffffu, a1, ofs);
        a2 += __shfl_xor_sync(0xffffffffu, a2, ofs);
        a3 += __shfl_xor_sync(0xffffffffu, a3, ofs);
        a4 += __shfl_xor_sync(0xffffffffu, a4, ofs);
        a5 += __shfl_xor_sync(0xffffffffu, a5, ofs);
        a6 += __shfl_xor_sync(0xffffffffu, a6, ofs);
        a7 += __shfl_xor_sync(0xffffffffu, a7, ofs);
        esum += __shfl_xor_sync(0xffffffffu, esum, ofs);
    }
    float inv = 1.f / (esum + EPSV);
    float4 b0 = reinterpret_cast<const float4*>(bias)[l * 2];
    float4 b1v = reinterpret_cast<const float4*>(bias)[l * 2 + 1];
    float r0 = fmaf(a0, inv, b0.x), r1 = fmaf(a1, inv, b0.y);
    float r2 = fmaf(a2, inv, b0.z), r3 = fmaf(a3, inv, b0.w);
    float r4 = fmaf(a4, inv, b1v.x), r5 = fmaf(a5, inv, b1v.y);
    float r6 = fmaf(a6, inv, b1v.z), r7 = fmaf(a7, inv, b1v.w);
    if (LAYER == 1) {
        if (sub == 0) {
            float4 o0 = make_float4(fmaxf(r0, 0.f), fmaxf(r1, 0.f), fmaxf(r2, 0.f), fmaxf(r3, 0.f));
            float4 o1 = make_float4(fmaxf(r4, 0.f), fmaxf(r5, 0.f), fmaxf(r6, 0.f), fmaxf(r7, 0.f));
            *reinterpret_cast<float4*>(&g_buf[d * 64 + l * 8]) = o0;
            *reinterpret_cast<float4*>(&g_buf[d * 64 + l * 8 + 4]) = o1;
        }
    } else {
        float m = fmaxf(fmaxf(fmaxf(r0, r1), fmaxf(r2, r3)),
                        fmaxf(fmaxf(r4, r5), fmaxf(r6, r7)));
#pragma unroll
        for (int ofs = 1; ofs < LPE; ofs <<= 1)
            m = fmaxf(m, __shfl_xor_sync(0xffffffffu, m, ofs));
        float ssum = expf(r0 - m) + expf(r1 - m) + expf(r2 - m) + expf(r3 - m)
                   + expf(r4 - m) + expf(r5 - m) + expf(r6 - m) + expf(r7 - m);
#pragma unroll
        for (int ofs = 1; ofs < LPE; ofs <<= 1)
            ssum += __shfl_xor_sync(0xffffffffu, ssum, ofs);
        float ls = m + logf(ssum);
        if (sub == 0) {
            float4 o0 = make_float4(r0 - ls, r1 - ls, r2 - ls, r3 - ls);
            float4 o1 = make_float4(r4 - ls, r5 - ls, r6 - ls, r7 - ls);
            *reinterpret_cast<float4*>(&out_arg[d * 32 + l * 8]) = o0;
            *reinterpret_cast<float4*>(&out_arg[d * 32 + l * 8 + 4]) = o1;
        }
    }
}

// ---------------- launch ----------------
static inline int cdiv(long long a, int b) { return (int)((a + b - 1) / b); }

extern "C" void kernel_launch(void* const* d_in, const int* in_sizes, int n_in,
                              void* d_out, int out_size) {
    const float* x      = (const float*)d_in[0];
    const int*   ei32   = (const int*)d_in[1];
    const float* W1     = (const float*)d_in[2];
    const float* a_src1 = (const float*)d_in[3];
    const float* a_dst1 = (const float*)d_in[4];
    const float* b1     = (const float*)d_in[5];
    const float* W2     = (const float*)d_in[6];
    const float* a_src2 = (const float*)d_in[7];
    const float* a_dst2 = (const float*)d_in[8];
    const float* b2     = (const float*)d_in[9];
    float* out = (float*)d_out;

    const int n = in_sizes[0] / 128;   // 50000
    const int E = 800000;
    const int Etot = E + n;            // 850000
    const int B = 256;

    // CSR build (shared by both layers)
    k_detect<<<1, 32>>>(ei32);
    k_build_hist<<<cdiv(Etot, B), B>>>(ei32, E, Etot);
    k_scan1<<<NBLK, SCB>>>(n);
    k_scan23<<<cdiv(n, B), B>>>(n, Etot);
    k_fill<<<cdiv(Etot, B), B>>>(ei32, E, Etot);

    // ---- layer 1 ----
    k_gemm_wmma<128, 64, 1><<<cdiv(n, 64), 128>>>(x, W1, a_src1, a_dst1, n);
    k_agg_csr<1><<<cdiv((long long)n * 32, B), B>>>(b1, nullptr, n);

    // ---- layer 2 ----
    k_gemm_wmma<64, 32, 2><<<cdiv(n, 64), 128>>>(nullptr, W2, a_src2, a_dst2, n);
    k_agg_csr<2><<<cdiv((long long)n * 32, B), B>>>(b2, out, n);
}

// round 12
// speedup vs baseline: 2.3397x; 1.0588x over previous
#include <cuda_runtime.h>
#include <cuda_fp16.h>
#include <mma.h>
#include <math.h>

using namespace nvcuda;

#define NN 50000
#define EE 800000
#define ETOT (EE + NN)
#define NH 4
#define NEG 0.2f
#define EPSV 1e-16f
#define SCB 1024
#define NBLK ((NN + SCB - 1) / SCB)   // 49
#define FLAGB 0x40000000

// ---------------- scratch (device globals; no allocation) ----------------
// NOTE: never pass these as kernel args from host code (host shadow symbol bug).
__device__ __half g_h1h[NN * 64];   // gemm out in fp16 (gather-only buffer)
__device__ float  g_buf[NN * 64];   // layer1 relu'd aggregated features (fp32)
__device__ float  g_als[NN * NH];
__device__ float  g_ald[NN * NH];
__device__ int    g_cnt[NN];        // zeroed at start; re-zeroed by k_scan each run
__device__ int    g_off[NN + 1];
__device__ int    g_cur[NN];
__device__ int    g_esrc[ETOT];
__device__ int    g_bsum[NBLK];     // lookback aggregates; re-zeroed by k_fill each run

// per-block redundant int64-vs-int32 detection (cheap; avoids a dedicated kernel)
__device__ __forceinline__ int detect_is64_block(const int* __restrict__ ei32, int* s_flag) {
    if (threadIdx.x == 0) {
        int all0 = 1;
        for (int j = 0; j < 32; j++)
            if (ei32[2 * j + 1] != 0) { all0 = 0; break; }
        *s_flag = all0;
    }
    __syncthreads();
    return *s_flag;
}

// ---------------- dst histogram (with inline detect) ----------------
__global__ void k_build_hist(const int* __restrict__ ei32, int E, int Etot) {
    __shared__ int s64;
    int is64 = detect_is64_block(ei32, &s64);
    int e = blockIdx.x * blockDim.x + threadIdx.x;
    if (e >= Etot) return;
    int d;
    if (e < E) d = is64 ? ei32[2 * (E + e)] : ei32[E + e];
    else       d = e - E;
    atomicAdd(&g_cnt[d], 1);
}

// ---------------- single-pass decoupled-lookback exclusive scan ----------------
// writes g_off (exclusive prefix), g_cur (copy), re-zeros g_cnt, sentinel g_off[n].
// All NBLK=49 blocks are co-resident (<<148 SMs) so spin-wait cannot deadlock.
__global__ void k_scan(int n, int Etot) {
    __shared__ int ws[32];
    __shared__ int s_pre;
    int t = threadIdx.x;
    int bid = blockIdx.x;
    int i = bid * SCB + t;
    int v = (i < n) ? g_cnt[i] : 0;
    int x = v;
#pragma unroll
    for (int ofs = 1; ofs < 32; ofs <<= 1) {
        int u = __shfl_up_sync(0xffffffffu, x, ofs);
        if ((t & 31) >= ofs) x += u;
    }
    if ((t & 31) == 31) ws[t >> 5] = x;
    __syncthreads();
    if (t < 32) {
        int y = ws[t];
#pragma unroll
        for (int ofs = 1; ofs < 32; ofs <<= 1) {
            int u = __shfl_up_sync(0xffffffffu, y, ofs);
            if (t >= ofs) y += u;
        }
        ws[t] = y;
    }
    __syncthreads();
    int base = (t >= 32) ? ws[(t >> 5) - 1] : 0;
    int incl = x + base;
    // post this block's aggregate (flagged)
    if (t == 0)
        atomicExch(&g_bsum[bid], ws[31] | FLAGB);
    // lookback: warp 0 sums all predecessor aggregates
    if (t < 32) {
        int pre = 0;
        for (int b0 = 0; b0 < bid; b0 += 32) {
            int j = b0 + t;
            int vv = 0;
            if (j < bid) {
                while (((vv = atomicAdd(&g_bsum[j], 0)) & FLAGB) == 0) { }
                vv &= ~FLAGB;
            }
#pragma unroll
            for (int ofs = 16; ofs; ofs >>= 1)
                vv += __shfl_xor_sync(0xffffffffu, vv, ofs);
            pre += vv;
        }
        if (t == 0) s_pre = pre;
    }
    __syncthreads();
    int off = incl - v + s_pre;
    if (i < n) {
        g_off[i] = off;
        g_cur[i] = off;
        g_cnt[i] = 0;                  // restore for next replay
    }
    if (i == 0) g_off[n] = Etot;
}

// bucket-fill: src ids grouped by dst (+ reset g_bsum for next replay)
__global__ void k_fill(const int* __restrict__ ei32, int E, int Etot) {
    __shared__ int s64;
    int is64 = detect_is64_block(ei32, &s64);
    int e = blockIdx.x * blockDim.x + threadIdx.x;
    if (e < NBLK && blockIdx.x == 0) g_bsum[e] = 0;
    if (e >= Etot) return;
    int s, d;
    if (e < E) {
        if (is64) { s = ei32[2 * e]; d = ei32[2 * (E + e)]; }
        else      { s = ei32[e];     d = ei32[E + e]; }
    } else { s = d = e - E; }
    int pos = atomicAdd(&g_cur[d], 1);
    g_esrc[pos] = s;
}

// ---------------- wmma fp16 GEMM + fused logits, fp16 feature output ----------------
template <int KTOT, int COLS, int LAYER>
__global__ void k_gemm_wmma(const float* __restrict__ A_arg,
                            const float* __restrict__ W,
                            const float* __restrict__ asrc,
                            const float* __restrict__ adst, int n) {
    const float* A = (LAYER == 1) ? A_arg : g_buf;
    const int LDA = KTOT + 8;
    const int LDB = COLS + 8;
    const int LDC = COLS + 8;
    const int NF  = COLS / 16;
    __shared__ __align__(16) char sraw[64 * (KTOT + 8) * 2 + KTOT * (COLS + 8) * 2 >
                                       64 * (COLS + 8) * 4
                                       ? 64 * (KTOT + 8) * 2 + KTOT * (COLS + 8) * 2
                                       : 64 * (COLS + 8) * 4];
    __half* As = reinterpret_cast<__half*>(sraw);
    __half* Bs = reinterpret_cast<__half*>(sraw + 64 * LDA * 2);
    float*  Cs = reinterpret_cast<float*>(sraw);

    int tid = threadIdx.x;
    int w = tid >> 5;
    int rbase = blockIdx.x * 64;

    const int A4 = 64 * KTOT / 4;
#pragma unroll
    for (int j = 0; j < A4 / 128; j++) {
        int idx = tid + j * 128;
        int row = idx / (KTOT / 4), k4 = idx % (KTOT / 4);
        int rg = rbase + row;
        if (rg >= n) rg = n - 1;
        float4 v = *reinterpret_cast<const float4*>(&A[rg * KTOT + k4 * 4]);
        __half2 h0 = __floats2half2_rn(v.x, v.y);
        __half2 h1 = __floats2half2_rn(v.z, v.w);
        uint2 u;
        u.x = *reinterpret_cast<unsigned*>(&h0);
        u.y = *reinterpret_cast<unsigned*>(&h1);
        *reinterpret_cast<uint2*>(&As[row * LDA + k4 * 4]) = u;
    }
    const int B4 = KTOT * COLS / 4;
#pragma unroll
    for (int j = 0; j < B4 / 128; j++) {
        int idx = tid + j * 128;
        int row = idx / (COLS / 4), c4 = idx % (COLS / 4);
        float4 v = *reinterpret_cast<const float4*>(&W[row * COLS + c4 * 4]);
        __half2 h0 = __floats2half2_rn(v.x, v.y);
        __half2 h1 = __floats2half2_rn(v.z, v.w);
        uint2 u;
        u.x = *reinterpret_cast<unsigned*>(&h0);
        u.y = *reinterpret_cast<unsigned*>(&h1);
        *reinterpret_cast<uint2*>(&Bs[row * LDB + c4 * 4]) = u;
    }
    __syncthreads();

    wmma::fragment<wmma::accumulator, 16, 16, 16, float> c[NF];
#pragma unroll
    for (int j = 0; j < NF; j++) wmma::fill_fragment(c[j], 0.f);
#pragma unroll
    for (int k0 = 0; k0 < KTOT; k0 += 16) {
        wmma::fragment<wmma::matrix_a, 16, 16, 16, __half, wmma::row_major> a;
        wmma::load_matrix_sync(a, &As[w * 16 * LDA + k0], LDA);
#pragma unroll
        for (int j = 0; j < NF; j++) {
            wmma::fragment<wmma::matrix_b, 16, 16, 16, __half, wmma::row_major> b;
            wmma::load_matrix_sync(b, &Bs[k0 * LDB + j * 16], LDB);
            wmma::mma_sync(c[j], a, b, c[j]);
        }
    }
    __syncthreads();
#pragma unroll
    for (int j = 0; j < NF; j++)
        wmma::store_matrix_sync(&Cs[w * 16 * LDC + j * 16], c[j], LDC, wmma::mem_row_major);
    __syncthreads();

    const int CG  = COLS / 4;
    const int RPT = 64 * CG / 128;
    const int C   = COLS / NH;
    const int TXH = C / 4;
    int tx = tid % CG, ty = tid / CG;
    float4 sa = *reinterpret_cast<const float4*>(&asrc[tx * 4]);
    float4 da = *reinterpret_cast<const float4*>(&adst[tx * 4]);
    int h = tx / TXH;
#pragma unroll
    for (int i = 0; i < RPT; i++) {
        int row = ty * RPT + i;
        int r = rbase + row;
        float4 acc = *reinterpret_cast<const float4*>(&Cs[row * LDC + tx * 4]);
        float ps = acc.x * sa.x + acc.y * sa.y + acc.z * sa.z + acc.w * sa.w;
        float pd = acc.x * da.x + acc.y * da.y + acc.z * da.z + acc.w * da.w;
#pragma unroll
        for (int ofs = 1; ofs < TXH; ofs <<= 1) {
            ps += __shfl_xor_sync(0xffffffffu, ps, ofs);
            pd += __shfl_xor_sync(0xffffffffu, pd, ofs);
        }
        if (r < n) {
            __half2 ha = __floats2half2_rn(acc.x, acc.y);
            __half2 hb = __floats2half2_rn(acc.z, acc.w);
            uint2 u;
            u.x = *reinterpret_cast<unsigned*>(&ha);
            u.y = *reinterpret_cast<unsigned*>(&hb);
            *reinterpret_cast<uint2*>(&g_h1h[r * COLS + tx * 4]) = u;
            if ((tx & (TXH - 1)) == 0) {
                g_als[r * 4 + h] = ps;
                g_ald[r * 4 + h] = pd;
            }
        }
    }
}

// ---------------- CSR aggregation: one warp per dst node, fp16 gather ----------------
template <int LAYER>
__global__ void k_agg_csr(const float* __restrict__ bias, float* __restrict__ out_arg, int n) {
    const int HC   = (LAYER == 1) ? 64 : 32;
    const int C    = HC / NH;
    const int LPE  = HC / 8;
    const int SUBS = 32 / LPE;
    int warp = (blockIdx.x * blockDim.x + threadIdx.x) >> 5;
    if (warp >= n) return;
    int d = warp;
    int lane = threadIdx.x & 31;
    int sub = lane / LPE;
    int l = lane % LPE;
    int h = (l * 8) / C;
    float ald_v = g_ald[d * 4 + h];
    int off0 = g_off[d], off1 = g_off[d + 1];
    float a0 = 0.f, a1 = 0.f, a2 = 0.f, a3 = 0.f;
    float a4 = 0.f, a5 = 0.f, a6 = 0.f, a7 = 0.f;
    float esum = 0.f;
    for (int i = off0 + sub; i < off1; i += SUBS) {
        int s = g_esrc[i];
        float lg = g_als[s * 4 + h] + ald_v;
        lg = (lg >= 0.f) ? lg : NEG * lg;
        float ev = __expf(lg);
        esum += ev;
        uint4 raw = *reinterpret_cast<const uint4*>(&g_h1h[s * HC + l * 8]);
        float2 f0 = __half22float2(*reinterpret_cast<__half2*>(&raw.x));
        float2 f1 = __half22float2(*reinterpret_cast<__half2*>(&raw.y));
        float2 f2 = __half22float2(*reinterpret_cast<__half2*>(&raw.z));
        float2 f3 = __half22float2(*reinterpret_cast<__half2*>(&raw.w));
        a0 = fmaf(ev, f0.x, a0); a1 = fmaf(ev, f0.y, a1);
        a2 = fmaf(ev, f1.x, a2); a3 = fmaf(ev, f1.y, a3);
        a4 = fmaf(ev, f2.x, a4); a5 = fmaf(ev, f2.y, a5);
        a6 = fmaf(ev, f3.x, a6); a7 = fmaf(ev, f3.y, a7);
    }
#pragma unroll
    for (int ofs = LPE; ofs < 32; ofs <<= 1) {
        a0 += __shfl_xor_sync(0xffffffffu, a0, ofs);
        a1 += __shfl_xor_sync(0xffffffffu, a1, ofs);
        a2 += __shfl_xor_sync(0xffffffffu, a2, ofs);
        a3 += __shfl_xor_sync(0xffffffffu, a3, ofs);
        a4 += __shfl_xor_sync(0xffffffffu, a4, ofs);
        a5 += __shfl_xor_sync(0xffffffffu, a5, ofs);
        a6 += __shfl_xor_sync(0xffffffffu, a6, ofs);
        a7 += __shfl_xor_sync(0xffffffffu, a7, ofs);
        esum += __shfl_xor_sync(0xffffffffu, esum, ofs);
    }
    float inv = 1.f / (esum + EPSV);
    float4 b0 = reinterpret_cast<const float4*>(bias)[l * 2];
    float4 b1v = reinterpret_cast<const float4*>(bias)[l * 2 + 1];
    float r0 = fmaf(a0, inv, b0.x), r1 = fmaf(a1, inv, b0.y);
    float r2 = fmaf(a2, inv, b0.z), r3 = fmaf(a3, inv, b0.w);
    float r4 = fmaf(a4, inv, b1v.x), r5 = fmaf(a5, inv, b1v.y);
    float r6 = fmaf(a6, inv, b1v.z), r7 = fmaf(a7, inv, b1v.w);
    if (LAYER == 1) {
        if (sub == 0) {
            float4 o0 = make_float4(fmaxf(r0, 0.f), fmaxf(r1, 0.f), fmaxf(r2, 0.f), fmaxf(r3, 0.f));
            float4 o1 = make_float4(fmaxf(r4, 0.f), fmaxf(r5, 0.f), fmaxf(r6, 0.f), fmaxf(r7, 0.f));
            *reinterpret_cast<float4*>(&g_buf[d * 64 + l * 8]) = o0;
            *reinterpret_cast<float4*>(&g_buf[d * 64 + l * 8 + 4]) = o1;
        }
    } else {
        float m = fmaxf(fmaxf(fmaxf(r0, r1), fmaxf(r2, r3)),
                        fmaxf(fmaxf(r4, r5), fmaxf(r6, r7)));
#pragma unroll
        for (int ofs = 1; ofs < LPE; ofs <<= 1)
            m = fmaxf(m, __shfl_xor_sync(0xffffffffu, m, ofs));
        float ssum = expf(r0 - m) + expf(r1 - m) + expf(r2 - m) + expf(r3 - m)
                   + expf(r4 - m) + expf(r5 - m) + expf(r6 - m) + expf(r7 - m);
#pragma unroll
        for (int ofs = 1; ofs < LPE; ofs <<= 1)
            ssum += __shfl_xor_sync(0xffffffffu, ssum, ofs);
        float ls = m + logf(ssum);
        if (sub == 0) {
            float4 o0 = make_float4(r0 - ls, r1 - ls, r2 - ls, r3 - ls);
            float4 o1 = make_float4(r4 - ls, r5 - ls, r6 - ls, r7 - ls);
            *reinterpret_cast<float4*>(&out_arg[d * 32 + l * 8]) = o0;
            *reinterpret_cast<float4*>(&out_arg[d * 32 + l * 8 + 4]) = o1;
        }
    }
}

// ---------------- launch ----------------
static inline int cdiv(long long a, int b) { return (int)((a + b - 1) / b); }

extern "C" void kernel_launch(void* const* d_in, const int* in_sizes, int n_in,
                              void* d_out, int out_size) {
    const float* x      = (const float*)d_in[0];
    const int*   ei32   = (const int*)d_in[1];
    const float* W1     = (const float*)d_in[2];
    const float* a_src1 = (const float*)d_in[3];
    const float* a_dst1 = (const float*)d_in[4];
    const float* b1     = (const float*)d_in[5];
    const float* W2     = (const float*)d_in[6];
    const float* a_src2 = (const float*)d_in[7];
    const float* a_dst2 = (const float*)d_in[8];
    const float* b2     = (const float*)d_in[9];
    float* out = (float*)d_out;

    const int n = in_sizes[0] / 128;   // 50000
    const int E = 800000;
    const int Etot = E + n;            // 850000
    const int B = 256;

    // side stream + events (created once, outside capture on the first call;
    // identical captured work every call)
    static cudaStream_t s2 = nullptr;
    static cudaEvent_t evF = nullptr, evJ = nullptr;
    if (!s2) {
        cudaStreamCreateWithFlags(&s2, cudaStreamNonBlocking);
        cudaEventCreateWithFlags(&evF, cudaEventDisableTiming);
        cudaEventCreateWithFlags(&evJ, cudaEventDisableTiming);
    }

    // fork: CSR build on s2, gemm1 on main stream (independent work)
    cudaEventRecord(evF, 0);
    cudaStreamWaitEvent(s2, evF, 0);

    k_build_hist<<<cdiv(Etot, B), B, 0, s2>>>(ei32, E, Etot);
    k_scan<<<NBLK, SCB, 0, s2>>>(n, Etot);
    k_fill<<<cdiv(Etot, B), B, 0, s2>>>(ei32, E, Etot);
    cudaEventRecord(evJ, s2);

    k_gemm_wmma<128, 64, 1><<<cdiv(n, 64), 128>>>(x, W1, a_src1, a_dst1, n);

    // join
    cudaStreamWaitEvent(0, evJ, 0);

    // ---- layer 1 aggregation, layer 2 ----
    k_agg_csr<1><<<cdiv((long long)n * 32, B), B>>>(b1, nullptr, n);
    k_gemm_wmma<64, 32, 2><<<cdiv(n, 64), 128>>>(nullptr, W2, a_src2, a_dst2, n);
    k_agg_csr<2><<<cdiv((long long)n * 32, B), B>>>(b2, out, n);
}

// round 13
// speedup vs baseline: 2.4241x; 1.0361x over previous
#include <cuda_runtime.h>
#include <cuda_fp16.h>
#include <mma.h>
#include <math.h>

using namespace nvcuda;

#define NN 50000
#define EE 800000
#define ETOT (EE + NN)
#define NH 4
#define NEG 0.2f
#define EPSV 1e-16f
#define SCB 1024
#define NBLK ((NN + SCB - 1) / SCB)   // 49
#define FLAGB 0x40000000

// ---------------- scratch (device globals; no allocation) ----------------
// NOTE: never pass these as kernel args from host code (host shadow symbol bug).
__device__ __half g_h1h[NN * 64];   // gemm out in fp16 (gather-only buffer)
__device__ __half g_bufh[NN * 64];  // layer1 relu'd aggregated features (fp16)
__device__ float  g_als[NN * NH];
__device__ float  g_ald[NN * NH];
__device__ int    g_cnt[NN];        // zeroed at start; re-zeroed by k_scan each run
__device__ int    g_off[NN + 1];
__device__ int    g_cur[NN];
__device__ int    g_esrc[ETOT];
__device__ int    g_bsum[NBLK];     // lookback aggregates; re-zeroed by k_fill each run

__device__ __forceinline__ int detect_is64_block(const int* __restrict__ ei32, int* s_flag) {
    if (threadIdx.x == 0) {
        int all0 = 1;
        for (int j = 0; j < 32; j++)
            if (ei32[2 * j + 1] != 0) { all0 = 0; break; }
        *s_flag = all0;
    }
    __syncthreads();
    return *s_flag;
}

// ---------------- dst histogram, 2 edges/thread ----------------
__global__ void k_build_hist(const int* __restrict__ ei32, int E, int Etot) {
    __shared__ int s64;
    int is64 = detect_is64_block(ei32, &s64);
    int e = (blockIdx.x * blockDim.x + threadIdx.x) * 2;
    if (e >= Etot) return;
    int d0, d1;
    if (e < E) {                       // pairs never straddle (E even)
        if (is64) { int4 v = *reinterpret_cast<const int4*>(&ei32[2 * (E + e)]); d0 = v.x; d1 = v.z; }
        else      { int2 v = *reinterpret_cast<const int2*>(&ei32[E + e]);       d0 = v.x; d1 = v.y; }
    } else { d0 = e - E; d1 = e + 1 - E; }
    atomicAdd(&g_cnt[d0], 1);
    atomicAdd(&g_cnt[d1], 1);
}

// ---------------- single-pass decoupled-lookback exclusive scan ----------------
__global__ void k_scan(int n, int Etot) {
    __shared__ int ws[32];
    __shared__ int s_pre;
    int t = threadIdx.x;
    int bid = blockIdx.x;
    int i = bid * SCB + t;
    int v = (i < n) ? g_cnt[i] : 0;
    int x = v;
#pragma unroll
    for (int ofs = 1; ofs < 32; ofs <<= 1) {
        int u = __shfl_up_sync(0xffffffffu, x, ofs);
        if ((t & 31) >= ofs) x += u;
    }
    if ((t & 31) == 31) ws[t >> 5] = x;
    __syncthreads();
    if (t < 32) {
        int y = ws[t];
#pragma unroll
        for (int ofs = 1; ofs < 32; ofs <<= 1) {
            int u = __shfl_up_sync(0xffffffffu, y, ofs);
            if (t >= ofs) y += u;
        }
        ws[t] = y;
    }
    __syncthreads();
    int base = (t >= 32) ? ws[(t >> 5) - 1] : 0;
    int incl = x + base;
    if (t == 0)
        atomicExch(&g_bsum[bid], ws[31] | FLAGB);
    if (t < 32) {
        int pre = 0;
        for (int b0 = 0; b0 < bid; b0 += 32) {
            int j = b0 + t;
            int vv = 0;
            if (j < bid) {
                while (((vv = atomicAdd(&g_bsum[j], 0)) & FLAGB) == 0) { }
                vv &= ~FLAGB;
            }
#pragma unroll
            for (int ofs = 16; ofs; ofs >>= 1)
                vv += __shfl_xor_sync(0xffffffffu, vv, ofs);
            pre += vv;
        }
        if (t == 0) s_pre = pre;
    }
    __syncthreads();
    int off = incl - v + s_pre;
    if (i < n) {
        g_off[i] = off;
        g_cur[i] = off;
        g_cnt[i] = 0;
    }
    if (i == 0) g_off[n] = Etot;
}

// ---------------- bucket-fill, 2 edges/thread (+ g_bsum reset) ----------------
__global__ void k_fill(const int* __restrict__ ei32, int E, int Etot) {
    __shared__ int s64;
    int is64 = detect_is64_block(ei32, &s64);
    if (blockIdx.x == 0 && threadIdx.x < NBLK) g_bsum[threadIdx.x] = 0;
    int e = (blockIdx.x * blockDim.x + threadIdx.x) * 2;
    if (e >= Etot) return;
    int s0, s1, d0, d1;
    if (e < E) {
        if (is64) {
            int4 sv = *reinterpret_cast<const int4*>(&ei32[2 * e]);
            int4 dv = *reinterpret_cast<const int4*>(&ei32[2 * (E + e)]);
            s0 = sv.x; s1 = sv.z; d0 = dv.x; d1 = dv.z;
        } else {
            int2 sv = *reinterpret_cast<const int2*>(&ei32[e]);
            int2 dv = *reinterpret_cast<const int2*>(&ei32[E + e]);
            s0 = sv.x; s1 = sv.y; d0 = dv.x; d1 = dv.y;
        }
    } else { s0 = d0 = e - E; s1 = d1 = e + 1 - E; }
    int p0 = atomicAdd(&g_cur[d0], 1);
    g_esrc[p0] = s0;
    int p1 = atomicAdd(&g_cur[d1], 1);
    g_esrc[p1] = s1;
}

// ---------------- wmma fp16 GEMM, 128-row x 256-thread blocks ----------------
// LAYER=1: A = x (fp32 arg), KTOT=128 (2 chunks of 64), COLS=64
// LAYER=2: A = g_bufh (fp16),  KTOT=64  (1 chunk),      COLS=32
// Epilogue: fp16 feature store to g_h1h + fused per-head logits to g_als/g_ald.
template <int KTOT, int COLS, int LAYER>
__global__ void k_gemm_wmma(const float* __restrict__ A_arg,
                            const float* __restrict__ W,
                            const float* __restrict__ asrc,
                            const float* __restrict__ adst, int n) {
    const int KT  = (KTOT > 64) ? 64 : KTOT;   // k-chunk
    const int NCH = KTOT / KT;
    const int LDA = KT + 8;
    const int LDB = COLS + 8;
    const int LDC = COLS + 8;
    const int NF  = COLS / 16;
    const int ABBYTES = 128 * LDA * 2 + KTOT * LDB * 2;
    const int CBYTES  = 128 * LDC * 4;
    __shared__ __align__(16) char sraw[ABBYTES > CBYTES ? ABBYTES : CBYTES];
    __half* As = reinterpret_cast<__half*>(sraw);
    __half* Bs = reinterpret_cast<__half*>(sraw + 128 * LDA * 2);
    float*  Cs = reinterpret_cast<float*>(sraw);

    int tid = threadIdx.x;
    int w = tid >> 5;
    int rbase = blockIdx.x * 128;

    // load full W (KTOT x COLS) fp32 -> fp16
    const int B4 = KTOT * COLS / 4;
#pragma unroll
    for (int j = 0; j < (B4 + 255) / 256; j++) {
        int idx = tid + j * 256;
        if (idx < B4) {
            int row = idx / (COLS / 4), c4 = idx % (COLS / 4);
            float4 v = *reinterpret_cast<const float4*>(&W[row * COLS + c4 * 4]);
            __half2 h0 = __floats2half2_rn(v.x, v.y);
            __half2 h1 = __floats2half2_rn(v.z, v.w);
            uint2 u;
            u.x = *reinterpret_cast<unsigned*>(&h0);
            u.y = *reinterpret_cast<unsigned*>(&h1);
            *reinterpret_cast<uint2*>(&Bs[row * LDB + c4 * 4]) = u;
        }
    }

    wmma::fragment<wmma::accumulator, 16, 16, 16, float> c[NF];
#pragma unroll
    for (int j = 0; j < NF; j++) wmma::fill_fragment(c[j], 0.f);

#pragma unroll
    for (int ch = 0; ch < NCH; ch++) {
        __syncthreads();               // guard As reuse across chunks
        if (LAYER == 1) {
            // fp32 source: 128 rows x KT floats
            const int A4 = 128 * KT / 4;
#pragma unroll
            for (int j = 0; j < A4 / 256; j++) {
                int idx = tid + j * 256;
                int row = idx / (KT / 4), k4 = idx % (KT / 4);
                int rg = rbase + row;
                if (rg >= n) rg = n - 1;
                float4 v = *reinterpret_cast<const float4*>(&A_arg[rg * KTOT + ch * KT + k4 * 4]);
                __half2 h0 = __floats2half2_rn(v.x, v.y);
                __half2 h1 = __floats2half2_rn(v.z, v.w);
                uint2 u;
                u.x = *reinterpret_cast<unsigned*>(&h0);
                u.y = *reinterpret_cast<unsigned*>(&h1);
                *reinterpret_cast<uint2*>(&As[row * LDA + k4 * 4]) = u;
            }
        } else {
            // fp16 source: direct 16B copies (KT==KTOT==64)
            const int A8 = 128 * KT / 8;
#pragma unroll
            for (int j = 0; j < A8 / 256; j++) {
                int idx = tid + j * 256;
                int row = idx / (KT / 8), k8 = idx % (KT / 8);
                int rg = rbase + row;
                if (rg >= n) rg = n - 1;
                uint4 v = *reinterpret_cast<const uint4*>(&g_bufh[rg * 64 + k8 * 8]);
                *reinterpret_cast<uint4*>(&As[row * LDA + k8 * 8]) = v;
            }
        }
        __syncthreads();
#pragma unroll
        for (int k0 = 0; k0 < KT; k0 += 16) {
            wmma::fragment<wmma::matrix_a, 16, 16, 16, __half, wmma::row_major> a;
            wmma::load_matrix_sync(a, &As[w * 16 * LDA + k0], LDA);
#pragma unroll
            for (int j = 0; j < NF; j++) {
                wmma::fragment<wmma::matrix_b, 16, 16, 16, __half, wmma::row_major> b;
                wmma::load_matrix_sync(b, &Bs[(ch * KT + k0) * LDB + j * 16], LDB);
                wmma::mma_sync(c[j], a, b, c[j]);
            }
        }
    }
    __syncthreads();
#pragma unroll
    for (int j = 0; j < NF; j++)
        wmma::store_matrix_sync(&Cs[w * 16 * LDC + j * 16], c[j], LDC, wmma::mem_row_major);
    __syncthreads();

    // epilogue
    const int CG  = COLS / 4;           // 16 / 8
    const int RPT = 128 / (256 / CG);   // 8 / 4
    const int C   = COLS / NH;          // 16 / 8
    const int TXH = C / 4;              // 4 / 2
    int tx = tid % CG, ty = tid / CG;
    float4 sa = *reinterpret_cast<const float4*>(&asrc[tx * 4]);
    float4 da = *reinterpret_cast<const float4*>(&adst[tx * 4]);
    int h = tx / TXH;
#pragma unroll
    for (int i = 0; i < RPT; i++) {
        int row = ty * RPT + i;
        int r = rbase + row;
        float4 acc = *reinterpret_cast<const float4*>(&Cs[row * LDC + tx * 4]);
        float ps = acc.x * sa.x + acc.y * sa.y + acc.z * sa.z + acc.w * sa.w;
        float pd = acc.x * da.x + acc.y * da.y + acc.z * da.z + acc.w * da.w;
#pragma unroll
        for (int ofs = 1; ofs < TXH; ofs <<= 1) {
            ps += __shfl_xor_sync(0xffffffffu, ps, ofs);
            pd += __shfl_xor_sync(0xffffffffu, pd, ofs);
        }
        if (r < n) {
            __half2 ha = __floats2half2_rn(acc.x, acc.y);
            __half2 hb = __floats2half2_rn(acc.z, acc.w);
            uint2 u;
            u.x = *reinterpret_cast<unsigned*>(&ha);
            u.y = *reinterpret_cast<unsigned*>(&hb);
            *reinterpret_cast<uint2*>(&g_h1h[r * COLS + tx * 4]) = u;
            if ((tx & (TXH - 1)) == 0) {
                g_als[r * 4 + h] = ps;
                g_ald[r * 4 + h] = pd;
            }
        }
    }
}

// ---------------- CSR aggregation: one warp per dst node, fp16 gather ----------------
// LAYER=1: HC=64, epilogue relu -> g_bufh (fp16). LAYER=2: HC=32, log_softmax -> out.
template <int LAYER>
__global__ void k_agg_csr(const float* __restrict__ bias, float* __restrict__ out_arg, int n) {
    const int HC   = (LAYER == 1) ? 64 : 32;
    const int C    = HC / NH;
    const int LPE  = HC / 8;
    const int SUBS = 32 / LPE;
    int warp = (blockIdx.x * blockDim.x + threadIdx.x) >> 5;
    if (warp >= n) return;
    int d = warp;
    int lane = threadIdx.x & 31;
    int sub = lane / LPE;
    int l = lane % LPE;
    int h = (l * 8) / C;
    float ald_v = g_ald[d * 4 + h];
    int off0 = g_off[d], off1 = g_off[d + 1];
    float a0 = 0.f, a1 = 0.f, a2 = 0.f, a3 = 0.f;
    float a4 = 0.f, a5 = 0.f, a6 = 0.f, a7 = 0.f;
    float esum = 0.f;
    for (int i = off0 + sub; i < off1; i += SUBS) {
        int s = g_esrc[i];
        float lg = g_als[s * 4 + h] + ald_v;
        lg = (lg >= 0.f) ? lg : NEG * lg;
        float ev = __expf(lg);
        esum += ev;
        uint4 raw = *reinterpret_cast<const uint4*>(&g_h1h[s * HC + l * 8]);
        float2 f0 = __half22float2(*reinterpret_cast<__half2*>(&raw.x));
        float2 f1 = __half22float2(*reinterpret_cast<__half2*>(&raw.y));
        float2 f2 = __half22float2(*reinterpret_cast<__half2*>(&raw.z));
        float2 f3 = __half22float2(*reinterpret_cast<__half2*>(&raw.w));
        a0 = fmaf(ev, f0.x, a0); a1 = fmaf(ev, f0.y, a1);
        a2 = fmaf(ev, f1.x, a2); a3 = fmaf(ev, f1.y, a3);
        a4 = fmaf(ev, f2.x, a4); a5 = fmaf(ev, f2.y, a5);
        a6 = fmaf(ev, f3.x, a6); a7 = fmaf(ev, f3.y, a7);
    }
#pragma unroll
    for (int ofs = LPE; ofs < 32; ofs <<= 1) {
        a0 += __shfl_xor_sync(0xffffffffu, a0, ofs);
        a1 += __shfl_xor_sync(0xffffffffu, a1, ofs);
        a2 += __shfl_xor_sync(0xffffffffu, a2, ofs);
        a3 += __shfl_xor_sync(0xffffffffu, a3, ofs);
        a4 += __shfl_xor_sync(0xffffffffu, a4, ofs);
        a5 += __shfl_xor_sync(0xffffffffu, a5, ofs);
        a6 += __shfl_xor_sync(0xffffffffu, a6, ofs);
        a7 += __shfl_xor_sync(0xffffffffu, a7, ofs);
        esum += __shfl_xor_sync(0xffffffffu, esum, ofs);
    }
    float inv = 1.f / (esum + EPSV);
    float4 b0 = reinterpret_cast<const float4*>(bias)[l * 2];
    float4 b1v = reinterpret_cast<const float4*>(bias)[l * 2 + 1];
    float r0 = fmaf(a0, inv, b0.x), r1 = fmaf(a1, inv, b0.y);
    float r2 = fmaf(a2, inv, b0.z), r3 = fmaf(a3, inv, b0.w);
    float r4 = fmaf(a4, inv, b1v.x), r5 = fmaf(a5, inv, b1v.y);
    float r6 = fmaf(a6, inv, b1v.z), r7 = fmaf(a7, inv, b1v.w);
    if (LAYER == 1) {
        if (sub == 0) {
            __half2 p0 = __floats2half2_rn(fmaxf(r0, 0.f), fmaxf(r1, 0.f));
            __half2 p1 = __floats2half2_rn(fmaxf(r2, 0.f), fmaxf(r3, 0.f));
            __half2 p2 = __floats2half2_rn(fmaxf(r4, 0.f), fmaxf(r5, 0.f));
            __half2 p3 = __floats2half2_rn(fmaxf(r6, 0.f), fmaxf(r7, 0.f));
            uint4 u;
            u.x = *reinterpret_cast<unsigned*>(&p0);
            u.y = *reinterpret_cast<unsigned*>(&p1);
            u.z = *reinterpret_cast<unsigned*>(&p2);
            u.w = *reinterpret_cast<unsigned*>(&p3);
            *reinterpret_cast<uint4*>(&g_bufh[d * 64 + l * 8]) = u;
        }
    } else {
        float m = fmaxf(fmaxf(fmaxf(r0, r1), fmaxf(r2, r3)),
                        fmaxf(fmaxf(r4, r5), fmaxf(r6, r7)));
#pragma unroll
        for (int ofs = 1; ofs < LPE; ofs <<= 1)
            m = fmaxf(m, __shfl_xor_sync(0xffffffffu, m, ofs));
        float ssum = expf(r0 - m) + expf(r1 - m) + expf(r2 - m) + expf(r3 - m)
                   + expf(r4 - m) + expf(r5 - m) + expf(r6 - m) + expf(r7 - m);
#pragma unroll
        for (int ofs = 1; ofs < LPE; ofs <<= 1)
            ssum += __shfl_xor_sync(0xffffffffu, ssum, ofs);
        float ls = m + logf(ssum);
        if (sub == 0) {
            float4 o0 = make_float4(r0 - ls, r1 - ls, r2 - ls, r3 - ls);
            float4 o1 = make_float4(r4 - ls, r5 - ls, r6 - ls, r7 - ls);
            *reinterpret_cast<float4*>(&out_arg[d * 32 + l * 8]) = o0;
            *reinterpret_cast<float4*>(&out_arg[d * 32 + l * 8 + 4]) = o1;
        }
    }
}

// ---------------- launch ----------------
static inline int cdiv(long long a, int b) { return (int)((a + b - 1) / b); }

extern "C" void kernel_launch(void* const* d_in, const int* in_sizes, int n_in,
                              void* d_out, int out_size) {
    const float* x      = (const float*)d_in[0];
    const int*   ei32   = (const int*)d_in[1];
    const float* W1     = (const float*)d_in[2];
    const float* a_src1 = (const float*)d_in[3];
    const float* a_dst1 = (const float*)d_in[4];
    const float* b1     = (const float*)d_in[5];
    const float* W2     = (const float*)d_in[6];
    const float* a_src2 = (const float*)d_in[7];
    const float* a_dst2 = (const float*)d_in[8];
    const float* b2     = (const float*)d_in[9];
    float* out = (float*)d_out;

    const int n = in_sizes[0] / 128;   // 50000
    const int E = 800000;
    const int Etot = E + n;            // 850000
    const int B = 256;

    static cudaStream_t s2 = nullptr;
    static cudaEvent_t evF = nullptr, evJ = nullptr;
    if (!s2) {
        cudaStreamCreateWithFlags(&s2, cudaStreamNonBlocking);
        cudaEventCreateWithFlags(&evF, cudaEventDisableTiming);
        cudaEventCreateWithFlags(&evJ, cudaEventDisableTiming);
    }

    // fork: CSR build on s2, gemm1 on main stream
    cudaEventRecord(evF, 0);
    cudaStreamWaitEvent(s2, evF, 0);

    k_build_hist<<<cdiv(Etot / 2, B), B, 0, s2>>>(ei32, E, Etot);
    k_scan<<<NBLK, SCB, 0, s2>>>(n, Etot);
    k_fill<<<cdiv(Etot / 2, B), B, 0, s2>>>(ei32, E, Etot);
    cudaEventRecord(evJ, s2);

    k_gemm_wmma<128, 64, 1><<<cdiv(n, 128), 256>>>(x, W1, a_src1, a_dst1, n);

    cudaStreamWaitEvent(0, evJ, 0);

    k_agg_csr<1><<<cdiv((long long)n * 32, B), B>>>(b1, nullptr, n);
    k_gemm_wmma<64, 32, 2><<<cdiv(n, 128), 256>>>(nullptr, W2, a_src2, a_dst2, n);
    k_agg_csr<2><<<cdiv((long long)n * 32, B), B>>>(b2, out, n);
}